// round 9
// baseline (speedup 1.0000x reference)
#include <cuda_runtime.h>
#include <cooperative_groups.h>
#include <cstdint>

namespace cg = cooperative_groups;

#define Bb 128
#define Tt 1024
#define Dd 256
#define Hh 256
#define Gg 1024  // 4H

typedef unsigned long long ull;

// 512 MB scratch for xg = x @ Wi
__device__ float g_xg[(size_t)Bb * Tt * Gg];

// ---- packed fp32x2 helpers (SASS FFMA2 — only reachable via PTX) ----
#define FMA2(d, a, b) \
  asm("fma.rn.f32x2 %0, %1, %2, %0;" : "+l"(d) : "l"(a), "l"(b))

__device__ __forceinline__ ull pack_dup(float x) {
  ull d;
  unsigned u = __float_as_uint(x);
  asm("mov.b64 %0, {%1, %1};" : "=l"(d) : "r"(u));
  return d;
}
__device__ __forceinline__ float2 unpack2(ull v) {
  float2 r;
  asm("mov.b64 {%0, %1}, %2;" : "=f"(r.x), "=f"(r.y) : "l"(v));
  return r;
}

// ---------------------------------------------------------------------------
// Kernel A: xg[m, g] = sum_d x[m, d] * Wi[d, g]   (unchanged, proven)
// ---------------------------------------------------------------------------
__global__ __launch_bounds__(256, 2) void xg_gemm(const float* __restrict__ X,
                                                  const float* __restrict__ Wi) {
  __shared__ float As[16][132];
  __shared__ float Bs[16][128];

  const int tid = threadIdx.x;
  const size_t mbase = (size_t)blockIdx.y * 128;
  const int nbase = blockIdx.x * 128;
  const float* A0 = X + mbase * Dd;
  const float* B0 = Wi + nbase;

  const int arow = tid >> 2;
  const int acol = (tid & 3) << 2;
  const int brow = tid >> 5;
  const int bcol = (tid & 31) << 2;
  const int tx = tid & 15;
  const int ty = tid >> 4;

  ull acc[8][4];
#pragma unroll
  for (int i = 0; i < 8; i++)
#pragma unroll
    for (int j = 0; j < 4; j++) acc[i][j] = 0ull;

  for (int k0 = 0; k0 < Dd; k0 += 16) {
#pragma unroll
    for (int i = 0; i < 2; i++) {
      float4 a = *(const float4*)(A0 + (size_t)(arow + i * 64) * Dd + k0 + acol);
      As[acol + 0][arow + i * 64] = a.x;
      As[acol + 1][arow + i * 64] = a.y;
      As[acol + 2][arow + i * 64] = a.z;
      As[acol + 3][arow + i * 64] = a.w;
    }
#pragma unroll
    for (int i = 0; i < 2; i++) {
      *(float4*)&Bs[brow + i * 8][bcol] =
          *(const float4*)(B0 + (size_t)(k0 + brow + i * 8) * Gg + bcol);
    }
    __syncthreads();
#pragma unroll
    for (int k = 0; k < 16; k++) {
      float ra[8];
      *(float4*)&ra[0] = *(const float4*)&As[k][ty * 8];
      *(float4*)&ra[4] = *(const float4*)&As[k][ty * 8 + 4];
      ulonglong2 rb0 = *(const ulonglong2*)&Bs[k][tx * 8];
      ulonglong2 rb1 = *(const ulonglong2*)&Bs[k][tx * 8 + 4];
      ull ra2[8];
#pragma unroll
      for (int i = 0; i < 8; i++) ra2[i] = pack_dup(ra[i]);
#pragma unroll
      for (int i = 0; i < 8; i++) {
        FMA2(acc[i][0], ra2[i], rb0.x);
        FMA2(acc[i][1], ra2[i], rb0.y);
        FMA2(acc[i][2], ra2[i], rb1.x);
        FMA2(acc[i][3], ra2[i], rb1.y);
      }
    }
    __syncthreads();
  }

  float* C = g_xg + (mbase + (size_t)ty * 8) * Gg + nbase + tx * 8;
#pragma unroll
  for (int i = 0; i < 8; i++) {
    float2 p0 = unpack2(acc[i][0]);
    float2 p1 = unpack2(acc[i][1]);
    float2 p2 = unpack2(acc[i][2]);
    float2 p3 = unpack2(acc[i][3]);
    *(float4*)(C + (size_t)i * Gg) = make_float4(p0.x, p0.y, p1.x, p1.y);
    *(float4*)(C + (size_t)i * Gg + 4) = make_float4(p2.x, p2.y, p3.x, p3.y);
  }
}

// ---------------------------------------------------------------------------
// Kernel B: persistent cluster LSTM, two batch groups software-pipelined.
// 16 clusters x 8 CTAs x 256 threads. CTA r owns gate cols {g*256+r*32..+32}.
// Group A = batches 0-3, group B = 4-7 of the cluster. Per step:
//   waitA -> gemmA -> updateA/pushA/arriveA -> waitB -> gemmB -> updateB/...
// Exchange latency of one group hides under the other group's compute.
// Sync: per-group double-buffered mbarriers, arrive-count=32 (8 CTA x 4 warps),
// plain DSMEM stores + __syncwarp + lane0 fence.acq_rel.cluster + arrives.
// ---------------------------------------------------------------------------

// SMEM float offsets
#define WHS_OFF 0        // [64 kc][128 col][4]  = 32768 (128 KB)
#define HBA_OFF 32768    // [2][4 b][256 k]      =  2048
#define HBB_OFF 34816    // [2][4 b][256 k]      =  2048
#define PART_OFF 36864   // [8 ks][4 b][128 col] =  4096 (shared A/B)
#define SMEM_FLOATS 40960
#define MB_BYTE (SMEM_FLOATS * 4)  // 4 mbarriers: A0 A1 B0 B1
#define SMEM_BYTES (MB_BYTE + 32)

__device__ __forceinline__ void mbar_init_(uint32_t a, uint32_t cnt) {
  asm volatile("mbarrier.init.shared.b64 [%0], %1;" ::"r"(a), "r"(cnt)
               : "memory");
}
__device__ __forceinline__ void mbar_wait_cluster(uint32_t mbar,
                                                  uint32_t parity) {
  asm volatile(
      "{\n\t"
      ".reg .pred P;\n\t"
      "WL_%=:\n\t"
      "mbarrier.try_wait.parity.acquire.cluster.shared::cta.b64 P, [%0], %1, 0x989680;\n\t"
      "@P bra.uni WD_%=;\n\t"
      "bra.uni WL_%=;\n\t"
      "WD_%=:\n\t"
      "}" ::"r"(mbar),
      "r"(parity)
      : "memory");
}
__device__ __forceinline__ uint32_t mapa_u32(uint32_t la, int rk) {
  uint32_t ra;
  asm("mapa.shared::cluster.u32 %0, %1, %2;" : "=r"(ra) : "r"(la), "r"(rk));
  return ra;
}
__device__ __forceinline__ void st_cluster_f32(uint32_t ra, float v) {
  asm volatile("st.shared::cluster.b32 [%0], %1;" ::"r"(ra),
               "r"(__float_as_uint(v))
               : "memory");
}
__device__ __forceinline__ void mbar_arrive_remote(uint32_t ra) {
  asm volatile("mbarrier.arrive.shared::cluster.b64 _, [%0];" ::"r"(ra)
               : "memory");
}

__device__ __forceinline__ float sigf(float x) {
  return 1.f / (1.f + __expf(-x));
}
__device__ __forceinline__ float tanhf_(float x) {
  return 2.f / (1.f + __expf(-2.f * x)) - 1.f;
}

// GEMM for one group: 4 batches x 4 gate-aligned cols x 32 k per thread.
__device__ __forceinline__ void gemm4(const float* __restrict__ whs,
                                      const float* __restrict__ hsrc,
                                      float* __restrict__ part, int kc0,
                                      int cg2, int ks) {
  const ulonglong2* w2 = (const ulonglong2*)whs;   // [kc][128]
  const ulonglong2* h2 = (const ulonglong2*)hsrc;  // [4][64]
  ull acc[4][4];
#pragma unroll
  for (int b = 0; b < 4; b++)
#pragma unroll
    for (int g = 0; g < 4; g++) acc[b][g] = 0ull;

#pragma unroll
  for (int kk = 0; kk < 8; kk++) {
    int kc = kc0 + kk;
    ulonglong2 w0 = w2[(kc << 7) + cg2];
    ulonglong2 w1 = w2[(kc << 7) + cg2 + 32];
    ulonglong2 wv = w2[(kc << 7) + cg2 + 64];
    ulonglong2 w3 = w2[(kc << 7) + cg2 + 96];
#pragma unroll
    for (int b = 0; b < 4; b++) {
      ulonglong2 hv = h2[(b << 6) + kc];
      FMA2(acc[b][0], hv.x, w0.x);
      FMA2(acc[b][0], hv.y, w0.y);
      FMA2(acc[b][1], hv.x, w1.x);
      FMA2(acc[b][1], hv.y, w1.y);
      FMA2(acc[b][2], hv.x, wv.x);
      FMA2(acc[b][2], hv.y, wv.y);
      FMA2(acc[b][3], hv.x, w3.x);
      FMA2(acc[b][3], hv.y, w3.y);
    }
  }
#pragma unroll
  for (int b = 0; b < 4; b++)
#pragma unroll
    for (int g = 0; g < 4; g++) {
      float2 s = unpack2(acc[b][g]);
      part[(ks << 9) + (b << 7) + (g << 5) + cg2] = s.x + s.y;
    }
}

// Update for one group: gate reduce + nonlinearity; returns new h.
__device__ __forceinline__ float lstm_update(const float* __restrict__ part,
                                             const float* xr,
                                             const float* breg, float& creg,
                                             int ub, int jj) {
  float g0 = xr[0] + breg[0], g1 = xr[1] + breg[1];
  float g2 = xr[2] + breg[2], g3 = xr[3] + breg[3];
#pragma unroll
  for (int s = 0; s < 8; s++) {
    const float* pc = part + (s << 9) + (ub << 7) + jj;
    g0 += pc[0];
    g1 += pc[32];
    g2 += pc[64];
    g3 += pc[96];
  }
  float iv = sigf(g0);
  float fv = sigf(g1);
  float zv = tanhf_(g2);
  float ov = sigf(g3);
  float cnew = fv * creg + iv * zv;
  creg = cnew;
  return ov * tanhf_(cnew);
}

// Push h to all 8 ranks + per-warp fenced arrivals on their group barrier.
__device__ __forceinline__ void push_h(uint32_t dst_u32, float hv,
                                       uint32_t bar_u32, int tid) {
#pragma unroll
  for (int i = 0; i < 8; i++) {
    int rk = (i + tid) & 7;
    st_cluster_f32(mapa_u32(dst_u32, rk), hv);
  }
  __syncwarp();
  if ((tid & 31) == 0) {
    asm volatile("fence.acq_rel.cluster;" ::: "memory");
#pragma unroll
    for (int rk = 0; rk < 8; rk++) mbar_arrive_remote(mapa_u32(bar_u32, rk));
  }
}

__global__ __launch_bounds__(256, 1) __cluster_dims__(8, 1, 1)
void lstm_rec(const float* __restrict__ Wh, const float* __restrict__ bh,
              float* __restrict__ out) {
  extern __shared__ float sm[];
  float* whs = sm + WHS_OFF;
  float* hbA = sm + HBA_OFF;
  float* hbB = sm + HBB_OFF;
  float* part = sm + PART_OFF;

  const int r = blockIdx.x;
  const int cl = blockIdx.y;
  const int tid = threadIdx.x;
  const uint32_t smb = (uint32_t)__cvta_generic_to_shared(sm);

  // ---- one-time init ----
  for (int idx = tid; idx < 32768; idx += 256) {
    int c = idx & 127;
    int k = idx >> 7;
    int gcol = ((c >> 5) << 8) + (r << 5) + (c & 31);
    whs[((k >> 2) << 9) + (c << 2) + (k & 3)] = Wh[k * Gg + gcol];
  }
  for (int idx = tid; idx < 2048; idx += 256) {
    hbA[idx] = 0.f;
    hbB[idx] = 0.f;
  }
  if (tid == 0) {
#pragma unroll
    for (int i = 0; i < 4; i++) mbar_init_(smb + MB_BYTE + (i << 3), 32);
  }

  // update mapping: thread (ub = tid>>5 in 0..3, jj = tid&31), tid<128 only
  const bool upd = tid < 128;
  const int ub = (tid >> 5) & 3;
  const int jj = tid & 31;
  const int m = (r << 5) + jj;
  float breg[4];
#pragma unroll
  for (int g = 0; g < 4; g++) breg[g] = bh[(g << 8) + m];

  // GEMM mapping
  const int ks = tid >> 5;
  const int cg2 = tid & 31;
  const int kc0 = ks << 3;

  cg::this_cluster().sync();  // init + mbarriers visible cluster-wide

  const size_t OUT_FIN = (size_t)Bb * Tt * Hh;
  const size_t gbA = (size_t)(cl << 3) + ub;
  const size_t gbB = gbA + 4;
  const float* xA = g_xg + gbA * Tt * Gg + m;
  const float* xB = g_xg + gbB * Tt * Gg + m;
  float* const outA = out + gbA * Tt * Hh + m;
  float* const outB = out + gbB * Tt * Hh + m;

  float cA = 0.f, cB = 0.f;
  int pA0 = 0, pA1 = 0, pB0 = 0, pB1 = 0;

  for (int t = 0; t < Tt; t++) {
    const int q = t & 1;
    const int qn = q ^ 1;
    const uint32_t barA = smb + MB_BYTE + (q << 3);
    const uint32_t barB = smb + MB_BYTE + 16 + (q << 3);
    const uint32_t barAn = smb + MB_BYTE + (qn << 3);
    const uint32_t barBn = smb + MB_BYTE + 16 + (qn << 3);

    // xg loads early: DRAM latency hides under wait + gemmA
    float xrA[4], xrB[4];
    if (upd) {
#pragma unroll
      for (int g = 0; g < 4; g++) {
        xrA[g] = __ldg(xA + (size_t)t * Gg + (g << 8));
        xrB[g] = __ldg(xB + (size_t)t * Gg + (g << 8));
      }
    }

    // ---- group A ----
    if (t) {
      mbar_wait_cluster(barA, q ? pA1 : pA0);
      if (q) pA1 ^= 1; else pA0 ^= 1;
    }
    __syncthreads();  // part WAR vs prev updateB reads

    gemm4(whs, hbA + q * 1024, part, kc0, cg2, ks);
    __syncthreads();  // part RAW

    if (upd) {
      float hv = lstm_update(part, xrA, breg, cA, ub, jj);
      if (t + 1 < Tt) {
        uint32_t dst = smb + ((HBA_OFF + qn * 1024 + (ub << 8) + m) << 2);
        push_h(dst, hv, barAn, tid);
      }
      outA[(size_t)t * Hh] = hv;
      if (t == Tt - 1) {
        out[OUT_FIN + gbA * Hh + m] = cA;
        out[OUT_FIN + (size_t)Bb * Hh + gbA * Hh + m] = hv;
      }
    }

    // ---- group B ----
    if (t) {
      mbar_wait_cluster(barB, q ? pB1 : pB0);
      if (q) pB1 ^= 1; else pB0 ^= 1;
    }
    __syncthreads();  // part WAR vs updateA reads

    gemm4(whs, hbB + q * 1024, part, kc0, cg2, ks);
    __syncthreads();  // part RAW

    if (upd) {
      float hv = lstm_update(part, xrB, breg, cB, ub, jj);
      if (t + 1 < Tt) {
        uint32_t dst = smb + ((HBB_OFF + qn * 1024 + (ub << 8) + m) << 2);
        push_h(dst, hv, barBn, tid);
      }
      outB[(size_t)t * Hh] = hv;
      if (t == Tt - 1) {
        out[OUT_FIN + gbB * Hh + m] = cB;
        out[OUT_FIN + (size_t)Bb * Hh + gbB * Hh + m] = hv;
      }
    }
  }

  cg::this_cluster().sync();  // no CTA exits with peer traffic in flight
}

// ---------------------------------------------------------------------------
extern "C" void kernel_launch(void* const* d_in, const int* in_sizes, int n_in,
                              void* d_out, int out_size) {
  const float* x = (const float*)d_in[0];    // [B, T, D]
  const float* Wi = (const float*)d_in[1];   // [D, 4H]
  const float* Wh = (const float*)d_in[2];   // [H, 4H]
  const float* bh = (const float*)d_in[3];   // [4H]
  float* out = (float*)d_out;                // outputs | c_fin | h_fin

  dim3 gA(Gg / 128, (Bb * Tt) / 128);  // (8, 1024)
  xg_gemm<<<gA, 256>>>(x, Wi);

  cudaFuncSetAttribute(lstm_rec, cudaFuncAttributeMaxDynamicSharedMemorySize,
                       SMEM_BYTES);
  lstm_rec<<<dim3(8, 16), 256, SMEM_BYTES>>>(Wh, bh, out);
}

// round 10
// speedup vs baseline: 1.5892x; 1.5892x over previous
#include <cuda_runtime.h>
#include <cooperative_groups.h>
#include <cstdint>

namespace cg = cooperative_groups;

#define Bb 128
#define Tt 1024
#define Dd 256
#define Hh 256
#define Gg 1024  // 4H

typedef unsigned long long ull;

// 512 MB scratch for xg = x @ Wi
__device__ float g_xg[(size_t)Bb * Tt * Gg];

// ---- packed fp32x2 helpers (SASS FFMA2 — only reachable via PTX) ----
#define FMA2(d, a, b) \
  asm("fma.rn.f32x2 %0, %1, %2, %0;" : "+l"(d) : "l"(a), "l"(b))

__device__ __forceinline__ ull pack_dup(float x) {
  ull d;
  unsigned u = __float_as_uint(x);
  asm("mov.b64 %0, {%1, %1};" : "=l"(d) : "r"(u));
  return d;
}
__device__ __forceinline__ float2 unpack2(ull v) {
  float2 r;
  asm("mov.b64 {%0, %1}, %2;" : "=f"(r.x), "=f"(r.y) : "l"(v));
  return r;
}

// ---------------------------------------------------------------------------
// Kernel A: xg[m, g] = sum_d x[m, d] * Wi[d, g]   (M=131072, N=1024, K=256)
// BM=BN=128, BK=16, 8x8 microtile, FFMA2. NO min-blocks clamp: the FFMA2
// variant needs ~130 regs; a 128-reg cap (occ 2) forces spills on every tile.
// ---------------------------------------------------------------------------
__global__ __launch_bounds__(256) void xg_gemm(const float* __restrict__ X,
                                               const float* __restrict__ Wi) {
  __shared__ float As[16][132];
  __shared__ float Bs[16][128];

  const int tid = threadIdx.x;
  const size_t mbase = (size_t)blockIdx.y * 128;
  const int nbase = blockIdx.x * 128;
  const float* A0 = X + mbase * Dd;
  const float* B0 = Wi + nbase;

  const int arow = tid >> 2;
  const int acol = (tid & 3) << 2;
  const int brow = tid >> 5;
  const int bcol = (tid & 31) << 2;
  const int tx = tid & 15;
  const int ty = tid >> 4;

  ull acc[8][4];
#pragma unroll
  for (int i = 0; i < 8; i++)
#pragma unroll
    for (int j = 0; j < 4; j++) acc[i][j] = 0ull;

  for (int k0 = 0; k0 < Dd; k0 += 16) {
#pragma unroll
    for (int i = 0; i < 2; i++) {
      float4 a = *(const float4*)(A0 + (size_t)(arow + i * 64) * Dd + k0 + acol);
      As[acol + 0][arow + i * 64] = a.x;
      As[acol + 1][arow + i * 64] = a.y;
      As[acol + 2][arow + i * 64] = a.z;
      As[acol + 3][arow + i * 64] = a.w;
    }
#pragma unroll
    for (int i = 0; i < 2; i++) {
      *(float4*)&Bs[brow + i * 8][bcol] =
          *(const float4*)(B0 + (size_t)(k0 + brow + i * 8) * Gg + bcol);
    }
    __syncthreads();
#pragma unroll
    for (int k = 0; k < 16; k++) {
      float ra[8];
      *(float4*)&ra[0] = *(const float4*)&As[k][ty * 8];
      *(float4*)&ra[4] = *(const float4*)&As[k][ty * 8 + 4];
      ulonglong2 rb0 = *(const ulonglong2*)&Bs[k][tx * 8];
      ulonglong2 rb1 = *(const ulonglong2*)&Bs[k][tx * 8 + 4];
#pragma unroll
      for (int i = 0; i < 8; i++) {
        ull ra2 = pack_dup(ra[i]);
        FMA2(acc[i][0], ra2, rb0.x);
        FMA2(acc[i][1], ra2, rb0.y);
        FMA2(acc[i][2], ra2, rb1.x);
        FMA2(acc[i][3], ra2, rb1.y);
      }
    }
    __syncthreads();
  }

  float* C = g_xg + (mbase + (size_t)ty * 8) * Gg + nbase + tx * 8;
#pragma unroll
  for (int i = 0; i < 8; i++) {
    float2 p0 = unpack2(acc[i][0]);
    float2 p1 = unpack2(acc[i][1]);
    float2 p2 = unpack2(acc[i][2]);
    float2 p3 = unpack2(acc[i][3]);
    *(float4*)(C + (size_t)i * Gg) = make_float4(p0.x, p0.y, p1.x, p1.y);
    *(float4*)(C + (size_t)i * Gg + 4) = make_float4(p2.x, p2.y, p3.x, p3.y);
  }
}

// ---------------------------------------------------------------------------
// Kernel B: persistent cluster LSTM recurrence (R6 skeleton).
// 16 clusters x 8 CTAs x 256 threads. CTA r owns gate cols {g*256+r*32..+32}.
// GEMM remap vs R6: thread (ks=tid>>6, c=tid&63) -> cols {c, c+64} x 8 batches
//   over k in [ks*64, ks*64+64). Crossbar = 2048 wf/step == FFMA2 issue floor
//   (R6 was 3072). acc = 16 ull = 32 regs (no spills, unlike R8's 64).
// Update: thread (ub=tid>>5, jj=tid&31) owns one h element, c-state in reg.
// Exchange: plain DSMEM stores to 8 ranks + split barrier.cluster arrive/wait
//   (release/acquire); wait doubles as the block-wide barrier for part WAR.
// ---------------------------------------------------------------------------

// SMEM float offsets
#define WHS_OFF 0        // [64 kc][128 col][4]   = 32768 (128 KB)
#define HB_OFF 32768     // [2][8 b][256 k]       =  4096 (16 KB)
#define PART_OFF 36864   // [4 ks][8 b][128 col]  =  4096 (16 KB)
#define XGS_OFF 40960    // [2][8 b][128 col]     =  2048 (8 KB)
#define SMEM_FLOATS 43008
#define SMEM_BYTES (SMEM_FLOATS * 4)

#define CLUSTER_ARRIVE() asm volatile("barrier.cluster.arrive.aligned;" ::: "memory")
#define CLUSTER_WAIT()   asm volatile("barrier.cluster.wait.aligned;" ::: "memory")

__device__ __forceinline__ float sigf(float x) {
  return 1.f / (1.f + __expf(-x));
}
__device__ __forceinline__ float tanhf_(float x) {
  return 2.f / (1.f + __expf(-2.f * x)) - 1.f;
}

__device__ __forceinline__ void prefetch_xg(float* dst, int cl, int r, int t,
                                            int tid) {
  int b = tid >> 5;
  int rem = tid & 31;
  int g = rem >> 3;
  int sub = rem & 7;
  size_t src = ((size_t)(cl * 8 + b) * Tt + t) * Gg + (g << 8) + (r << 5) +
               (sub << 2);
  unsigned saddr =
      (unsigned)__cvta_generic_to_shared(dst + (b << 7) + (g << 5) + (sub << 2));
  asm volatile("cp.async.cg.shared.global [%0], [%1], 16;\n" ::"r"(saddr),
               "l"(g_xg + src));
}

__global__ __launch_bounds__(256, 1) __cluster_dims__(8, 1, 1)
void lstm_rec(const float* __restrict__ Wh, const float* __restrict__ bh,
              float* __restrict__ out) {
  extern __shared__ float sm[];
  float* whs = sm + WHS_OFF;
  float* hb = sm + HB_OFF;
  float* part = sm + PART_OFF;
  float* xgs = sm + XGS_OFF;

  cg::cluster_group cluster = cg::this_cluster();
  const int r = blockIdx.x;
  const int cl = blockIdx.y;
  const int tid = threadIdx.x;

  // ---- one-time init: Wh slice [k/4][col][4], h0 = 0 ----
  for (int idx = tid; idx < 32768; idx += 256) {
    int c = idx & 127;
    int k = idx >> 7;
    int gcol = ((c >> 5) << 8) + (r << 5) + (c & 31);
    whs[((k >> 2) << 9) + (c << 2) + (k & 3)] = Wh[k * Gg + gcol];
  }
  for (int idx = tid; idx < 4096; idx += 256) hb[idx] = 0.f;

  // update mapping: one h element per thread
  const int ub = tid >> 5;  // batch 0..7
  const int jj = tid & 31;  // h column within CTA slice
  const int m = (r << 5) + jj;
  float breg[4];
#pragma unroll
  for (int g = 0; g < 4; g++) breg[g] = bh[(g << 8) + m];

  // GEMM mapping: 4-way k-split, 2 cols x 8 batches per thread
  const int ks = tid >> 6;  // 0..3
  const int cc = tid & 63;  // cols cc, cc+64
  const int kc0 = ks << 4;  // 16 kc (64 k) per thread

  // remote smem base pointers for h replication
  float* rank0 = cluster.map_shared_rank(hb, 0);
  float* rank1 = cluster.map_shared_rank(hb, 1);
  float* rank2 = cluster.map_shared_rank(hb, 2);
  float* rank3 = cluster.map_shared_rank(hb, 3);
  float* rank4 = cluster.map_shared_rank(hb, 4);
  float* rank5 = cluster.map_shared_rank(hb, 5);
  float* rank6 = cluster.map_shared_rank(hb, 6);
  float* rank7 = cluster.map_shared_rank(hb, 7);

  prefetch_xg(xgs, cl, r, 0, tid);
  asm volatile("cp.async.commit_group;" ::: "memory");

  cluster.sync();  // smem init visible cluster-wide before remote writes

  float creg = 0.f;
  const size_t OUT_FIN = (size_t)Bb * Tt * Hh;
  const size_t gb = (size_t)(cl << 3) + ub;
  float* const out_base = out + (gb << 10) * Hh + m;

  for (int t = 0; t < Tt; t++) {
    // wait(t): h(t) ready in hb[t&1]; also block-wide barrier (part WAR safe:
    // all threads' update(t-1) part-reads precede their arrive(t-1)).
    if (t) CLUSTER_WAIT();

    if (t + 1 < Tt) prefetch_xg(xgs + ((t + 1) & 1) * 1024, cl, r, t + 1, tid);
    asm volatile("cp.async.commit_group;" ::: "memory");

    // ---- GEMM: part[ks][b][{cc,cc+64}] over this thread's 64-k slice ----
    {
      const ulonglong2* w2 = (const ulonglong2*)whs;              // [kc][128]
      const ulonglong2* h2 = (const ulonglong2*)(hb + (t & 1) * 2048);
      ull acc[8][2];
#pragma unroll
      for (int b = 0; b < 8; b++) { acc[b][0] = 0ull; acc[b][1] = 0ull; }

#pragma unroll 4
      for (int kk = 0; kk < 16; kk++) {
        int kc = kc0 + kk;
        ulonglong2 w0 = w2[(kc << 7) + cc];
        ulonglong2 w1 = w2[(kc << 7) + cc + 64];
#pragma unroll
        for (int b = 0; b < 8; b++) {
          ulonglong2 hv = h2[(b << 6) + kc];
          FMA2(acc[b][0], hv.x, w0.x);
          FMA2(acc[b][0], hv.y, w0.y);
          FMA2(acc[b][1], hv.x, w1.x);
          FMA2(acc[b][1], hv.y, w1.y);
        }
      }
#pragma unroll
      for (int b = 0; b < 8; b++) {
        float2 s0 = unpack2(acc[b][0]);
        float2 s1 = unpack2(acc[b][1]);
        part[(ks << 10) + (b << 7) + cc] = s0.x + s0.y;
        part[(ks << 10) + (b << 7) + cc + 64] = s1.x + s1.y;
      }
    }

    asm volatile("cp.async.wait_group 1;" ::: "memory");
    __syncthreads();  // part RAW + xgs(t) visible

    // ---- update: reduce 4 k-partials per gate, nonlinearity, push ----
    {
      const float* xc = xgs + (t & 1) * 1024 + (ub << 7);
      float g0 = xc[jj] + breg[0];
      float g1 = xc[32 + jj] + breg[1];
      float g2 = xc[64 + jj] + breg[2];
      float g3 = xc[96 + jj] + breg[3];
#pragma unroll
      for (int s = 0; s < 4; s++) {
        const float* pc = part + (s << 10) + (ub << 7) + jj;
        g0 += pc[0];
        g1 += pc[32];
        g2 += pc[64];
        g3 += pc[96];
      }
      float iv = sigf(g0);
      float fv = sigf(g1);
      float zv = tanhf_(g2);
      float ov = sigf(g3);
      float cnew = fv * creg + iv * zv;
      creg = cnew;
      float hv = ov * tanhf_(cnew);

      if (t + 1 < Tt) {
        int off = ((t + 1) & 1) * 2048 + (ub << 8) + m;
        rank0[off] = hv;
        rank1[off] = hv;
        rank2[off] = hv;
        rank3[off] = hv;
        rank4[off] = hv;
        rank5[off] = hv;
        rank6[off] = hv;
        rank7[off] = hv;
        CLUSTER_ARRIVE();  // release: pushes visible at peers' wait(t+1)
      }

      // global stores off the sync path
      out_base[(size_t)t * Hh] = hv;
      if (t == Tt - 1) {
        out[OUT_FIN + gb * Hh + m] = cnew;
        out[OUT_FIN + (size_t)Bb * Hh + gb * Hh + m] = hv;
      }
    }
  }

  cluster.sync();  // no CTA exits while peer traffic could be in flight
}

// ---------------------------------------------------------------------------
extern "C" void kernel_launch(void* const* d_in, const int* in_sizes, int n_in,
                              void* d_out, int out_size) {
  const float* x = (const float*)d_in[0];    // [B, T, D]
  const float* Wi = (const float*)d_in[1];   // [D, 4H]
  const float* Wh = (const float*)d_in[2];   // [H, 4H]
  const float* bh = (const float*)d_in[3];   // [4H]
  float* out = (float*)d_out;                // outputs | c_fin | h_fin

  dim3 gA(Gg / 128, (Bb * Tt) / 128);  // (8, 1024)
  xg_gemm<<<gA, 256>>>(x, Wi);

  cudaFuncSetAttribute(lstm_rec, cudaFuncAttributeMaxDynamicSharedMemorySize,
                       SMEM_BYTES);
  lstm_rec<<<dim3(8, 16), 256, SMEM_BYTES>>>(Wh, bh, out);
}

// round 11
// speedup vs baseline: 1.7221x; 1.0836x over previous
#include <cuda_runtime.h>
#include <cooperative_groups.h>
#include <cstdint>

namespace cg = cooperative_groups;

#define Bb 128
#define Tt 1024
#define Dd 256
#define Hh 256
#define Gg 1024  // 4H

typedef unsigned long long ull;

// 512 MB scratch for xg = x @ Wi
__device__ float g_xg[(size_t)Bb * Tt * Gg];

// ---- packed fp32x2 helpers (SASS FFMA2 — only reachable via PTX) ----
#define FMA2(d, a, b) \
  asm("fma.rn.f32x2 %0, %1, %2, %0;" : "+l"(d) : "l"(a), "l"(b))

__device__ __forceinline__ ull pack_dup(float x) {
  ull d;
  unsigned u = __float_as_uint(x);
  asm("mov.b64 %0, {%1, %1};" : "=l"(d) : "r"(u));
  return d;
}
__device__ __forceinline__ float2 unpack2(ull v) {
  float2 r;
  asm("mov.b64 {%0, %1}, %2;" : "=f"(r.x), "=f"(r.y) : "l"(v));
  return r;
}

// ---------------------------------------------------------------------------
// Kernel A: xg[m, g] = sum_d x[m, d] * Wi[d, g]   (unchanged from R10)
// ---------------------------------------------------------------------------
__global__ __launch_bounds__(256) void xg_gemm(const float* __restrict__ X,
                                               const float* __restrict__ Wi) {
  __shared__ float As[16][132];
  __shared__ float Bs[16][128];

  const int tid = threadIdx.x;
  const size_t mbase = (size_t)blockIdx.y * 128;
  const int nbase = blockIdx.x * 128;
  const float* A0 = X + mbase * Dd;
  const float* B0 = Wi + nbase;

  const int arow = tid >> 2;
  const int acol = (tid & 3) << 2;
  const int brow = tid >> 5;
  const int bcol = (tid & 31) << 2;
  const int tx = tid & 15;
  const int ty = tid >> 4;

  ull acc[8][4];
#pragma unroll
  for (int i = 0; i < 8; i++)
#pragma unroll
    for (int j = 0; j < 4; j++) acc[i][j] = 0ull;

  for (int k0 = 0; k0 < Dd; k0 += 16) {
#pragma unroll
    for (int i = 0; i < 2; i++) {
      float4 a = *(const float4*)(A0 + (size_t)(arow + i * 64) * Dd + k0 + acol);
      As[acol + 0][arow + i * 64] = a.x;
      As[acol + 1][arow + i * 64] = a.y;
      As[acol + 2][arow + i * 64] = a.z;
      As[acol + 3][arow + i * 64] = a.w;
    }
#pragma unroll
    for (int i = 0; i < 2; i++) {
      *(float4*)&Bs[brow + i * 8][bcol] =
          *(const float4*)(B0 + (size_t)(k0 + brow + i * 8) * Gg + bcol);
    }
    __syncthreads();
#pragma unroll
    for (int k = 0; k < 16; k++) {
      float ra[8];
      *(float4*)&ra[0] = *(const float4*)&As[k][ty * 8];
      *(float4*)&ra[4] = *(const float4*)&As[k][ty * 8 + 4];
      ulonglong2 rb0 = *(const ulonglong2*)&Bs[k][tx * 8];
      ulonglong2 rb1 = *(const ulonglong2*)&Bs[k][tx * 8 + 4];
#pragma unroll
      for (int i = 0; i < 8; i++) {
        ull ra2 = pack_dup(ra[i]);
        FMA2(acc[i][0], ra2, rb0.x);
        FMA2(acc[i][1], ra2, rb0.y);
        FMA2(acc[i][2], ra2, rb1.x);
        FMA2(acc[i][3], ra2, rb1.y);
      }
    }
    __syncthreads();
  }

  float* C = g_xg + (mbase + (size_t)ty * 8) * Gg + nbase + tx * 8;
#pragma unroll
  for (int i = 0; i < 8; i++) {
    float2 p0 = unpack2(acc[i][0]);
    float2 p1 = unpack2(acc[i][1]);
    float2 p2 = unpack2(acc[i][2]);
    float2 p3 = unpack2(acc[i][3]);
    *(float4*)(C + (size_t)i * Gg) = make_float4(p0.x, p0.y, p1.x, p1.y);
    *(float4*)(C + (size_t)i * Gg + 4) = make_float4(p2.x, p2.y, p3.x, p3.y);
  }
}

// ---------------------------------------------------------------------------
// Kernel B: persistent cluster LSTM recurrence — 512 threads/CTA.
// 16 clusters x 8 CTAs. CTA r owns gate cols {g*256 + r*32 .. +32}.
// GEMM: thread (ks=tid>>6 in 0..7, cc=tid&63) -> cols {cc, cc+64} x 8 batches
//   over k in [ks*32, ks*32+32). Same per-SMSP FFMA2 count as R10 but 4
//   warps/SMSP interleave to cover LDS latency (issue 32% -> ~60%).
// Update (tid<256): thread (ub=tid>>5, jj=tid&31) owns one h element.
// Exchange: DSMEM stores to 8 ranks + split barrier.cluster arrive/wait.
// ---------------------------------------------------------------------------

// SMEM float offsets
#define WHS_OFF 0        // [64 kc][128 col][4]   = 32768 (128 KB)
#define HB_OFF 32768     // [2][8 b][256 k]       =  4096 (16 KB)
#define PART_OFF 36864   // [8 ks][8 b][128 col]  =  8192 (32 KB)
#define XGS_OFF 45056    // [2][8 b][128 col]     =  2048 (8 KB)
#define SMEM_FLOATS 47104
#define SMEM_BYTES (SMEM_FLOATS * 4)

#define CLUSTER_ARRIVE() asm volatile("barrier.cluster.arrive.aligned;" ::: "memory")
#define CLUSTER_WAIT()   asm volatile("barrier.cluster.wait.aligned;" ::: "memory")

__device__ __forceinline__ float sigf(float x) {
  return __fdividef(1.f, 1.f + __expf(-x));
}
__device__ __forceinline__ float tanhf_(float x) {
  return __fdividef(2.f, 1.f + __expf(-2.f * x)) - 1.f;
}

__device__ __forceinline__ void prefetch_xg(float* dst, int cl, int r, int t,
                                            int tid) {
  // 256 lanes move 8 batches x 128 cols (gate-sliced) as 16B chunks
  int b = tid >> 5;
  int rem = tid & 31;
  int g = rem >> 3;
  int sub = rem & 7;
  size_t src = ((size_t)(cl * 8 + b) * Tt + t) * Gg + (g << 8) + (r << 5) +
               (sub << 2);
  unsigned saddr =
      (unsigned)__cvta_generic_to_shared(dst + (b << 7) + (g << 5) + (sub << 2));
  asm volatile("cp.async.cg.shared.global [%0], [%1], 16;\n" ::"r"(saddr),
               "l"(g_xg + src));
}

__global__ __launch_bounds__(512, 1) __cluster_dims__(8, 1, 1)
void lstm_rec(const float* __restrict__ Wh, const float* __restrict__ bh,
              float* __restrict__ out) {
  extern __shared__ float sm[];
  float* whs = sm + WHS_OFF;
  float* hb = sm + HB_OFF;
  float* part = sm + PART_OFF;
  float* xgs = sm + XGS_OFF;

  cg::cluster_group cluster = cg::this_cluster();
  const int r = blockIdx.x;
  const int cl = blockIdx.y;
  const int tid = threadIdx.x;

  // ---- one-time init: Wh slice [k/4][col][4], h0 = 0 ----
  for (int idx = tid; idx < 32768; idx += 512) {
    int c = idx & 127;
    int k = idx >> 7;
    int gcol = ((c >> 5) << 8) + (r << 5) + (c & 31);
    whs[((k >> 2) << 9) + (c << 2) + (k & 3)] = Wh[k * Gg + gcol];
  }
  for (int idx = tid; idx < 4096; idx += 512) hb[idx] = 0.f;

  // update mapping (threads 0..255): one h element per thread
  const bool upd = tid < 256;
  const int ub = (tid >> 5) & 7;  // batch 0..7
  const int jj = tid & 31;        // h column within CTA slice
  const int m = (r << 5) + jj;
  float breg[4];
#pragma unroll
  for (int g = 0; g < 4; g++) breg[g] = bh[(g << 8) + m];

  // GEMM mapping: 8-way k-split, 2 cols x 8 batches per thread
  const int ks = tid >> 6;  // 0..7
  const int cc = tid & 63;  // cols cc, cc+64
  const int kc0 = ks << 3;  // 8 kc (32 k) per thread

  // remote smem base pointers for h replication
  float* rank0 = cluster.map_shared_rank(hb, 0);
  float* rank1 = cluster.map_shared_rank(hb, 1);
  float* rank2 = cluster.map_shared_rank(hb, 2);
  float* rank3 = cluster.map_shared_rank(hb, 3);
  float* rank4 = cluster.map_shared_rank(hb, 4);
  float* rank5 = cluster.map_shared_rank(hb, 5);
  float* rank6 = cluster.map_shared_rank(hb, 6);
  float* rank7 = cluster.map_shared_rank(hb, 7);

  if (upd) prefetch_xg(xgs, cl, r, 0, tid);
  asm volatile("cp.async.commit_group;" ::: "memory");

  cluster.sync();  // smem init visible cluster-wide before remote writes

  float creg = 0.f;
  const size_t OUT_FIN = (size_t)Bb * Tt * Hh;
  const size_t gb = (size_t)(cl << 3) + ub;
  float* const out_base = out + (gb << 10) * Hh + m;

  for (int t = 0; t < Tt; t++) {
    // wait(t): h(t) ready in hb[t&1]; doubles as part-WAR barrier
    if (t) CLUSTER_WAIT();

    if (upd && t + 1 < Tt)
      prefetch_xg(xgs + ((t + 1) & 1) * 1024, cl, r, t + 1, tid);
    asm volatile("cp.async.commit_group;" ::: "memory");

    // ---- GEMM: part[ks][b][{cc,cc+64}] over this thread's 32-k slice ----
    {
      const ulonglong2* w2 = (const ulonglong2*)whs;              // [kc][128]
      const ulonglong2* h2 = (const ulonglong2*)(hb + (t & 1) * 2048);
      ull acc[8][2];
#pragma unroll
      for (int b = 0; b < 8; b++) { acc[b][0] = 0ull; acc[b][1] = 0ull; }

#pragma unroll
      for (int kk = 0; kk < 8; kk++) {
        int kc = kc0 + kk;
        ulonglong2 w0 = w2[(kc << 7) + cc];
        ulonglong2 w1 = w2[(kc << 7) + cc + 64];
#pragma unroll
        for (int b = 0; b < 8; b++) {
          ulonglong2 hv = h2[(b << 6) + kc];
          FMA2(acc[b][0], hv.x, w0.x);
          FMA2(acc[b][0], hv.y, w0.y);
          FMA2(acc[b][1], hv.x, w1.x);
          FMA2(acc[b][1], hv.y, w1.y);
        }
      }
#pragma unroll
      for (int b = 0; b < 8; b++) {
        float2 s0 = unpack2(acc[b][0]);
        float2 s1 = unpack2(acc[b][1]);
        part[(ks << 10) + (b << 7) + cc] = s0.x + s0.y;
        part[(ks << 10) + (b << 7) + cc + 64] = s1.x + s1.y;
      }
    }

    asm volatile("cp.async.wait_group 1;" ::: "memory");
    __syncthreads();  // part RAW + xgs(t) visible

    // ---- update (tid<256): reduce 8 k-partials per gate, push h ----
    if (upd) {
      const float* xc = xgs + (t & 1) * 1024 + (ub << 7);
      float g0 = xc[jj] + breg[0];
      float g1 = xc[32 + jj] + breg[1];
      float g2 = xc[64 + jj] + breg[2];
      float g3 = xc[96 + jj] + breg[3];
#pragma unroll
      for (int s = 0; s < 8; s++) {
        const float* pc = part + (s << 10) + (ub << 7) + jj;
        g0 += pc[0];
        g1 += pc[32];
        g2 += pc[64];
        g3 += pc[96];
      }
      float iv = sigf(g0);
      float fv = sigf(g1);
      float zv = tanhf_(g2);
      float ov = sigf(g3);
      float cnew = fv * creg + iv * zv;
      creg = cnew;
      float hv = ov * tanhf_(cnew);

      if (t + 1 < Tt) {
        int off = ((t + 1) & 1) * 2048 + (ub << 8) + m;
        rank0[off] = hv;
        rank1[off] = hv;
        rank2[off] = hv;
        rank3[off] = hv;
        rank4[off] = hv;
        rank5[off] = hv;
        rank6[off] = hv;
        rank7[off] = hv;
      }

      // global stores off the sync path
      out_base[(size_t)t * Hh] = hv;
      if (t == Tt - 1) {
        out[OUT_FIN + gb * Hh + m] = cnew;
        out[OUT_FIN + (size_t)Bb * Hh + gb * Hh + m] = hv;
      }
    }

    // release: all threads arrive; pushes visible at peers' wait(t+1)
    if (t + 1 < Tt) CLUSTER_ARRIVE();
  }

  cluster.sync();  // no CTA exits while peer traffic could be in flight
}

// ---------------------------------------------------------------------------
extern "C" void kernel_launch(void* const* d_in, const int* in_sizes, int n_in,
                              void* d_out, int out_size) {
  const float* x = (const float*)d_in[0];    // [B, T, D]
  const float* Wi = (const float*)d_in[1];   // [D, 4H]
  const float* Wh = (const float*)d_in[2];   // [H, 4H]
  const float* bh = (const float*)d_in[3];   // [4H]
  float* out = (float*)d_out;                // outputs | c_fin | h_fin

  dim3 gA(Gg / 128, (Bb * Tt) / 128);  // (8, 1024)
  xg_gemm<<<gA, 256>>>(x, Wi);

  cudaFuncSetAttribute(lstm_rec, cudaFuncAttributeMaxDynamicSharedMemorySize,
                       SMEM_BYTES);
  lstm_rec<<<dim3(8, 16), 512, SMEM_BYTES>>>(Wh, bh, out);
}

// round 12
// speedup vs baseline: 1.8533x; 1.0762x over previous
#include <cuda_runtime.h>
#include <cooperative_groups.h>
#include <cstdint>

namespace cg = cooperative_groups;

#define Bb 128
#define Tt 1024
#define Dd 256
#define Hh 256
#define Gg 1024  // 4H

typedef unsigned long long ull;

// 512 MB scratch for xg = x @ Wi
__device__ float g_xg[(size_t)Bb * Tt * Gg];

// ---- packed fp32x2 helpers (SASS FFMA2 — only reachable via PTX) ----
#define FMA2(d, a, b) \
  asm("fma.rn.f32x2 %0, %1, %2, %0;" : "+l"(d) : "l"(a), "l"(b))

__device__ __forceinline__ ull pack_dup(float x) {
  ull d;
  unsigned u = __float_as_uint(x);
  asm("mov.b64 %0, {%1, %1};" : "=l"(d) : "r"(u));
  return d;
}
__device__ __forceinline__ ull pack2(float a, float b) {
  ull d;
  asm("mov.b64 %0, {%1, %2};" : "=l"(d) : "f"(a), "f"(b));
  return d;
}
__device__ __forceinline__ float2 unpack2(ull v) {
  float2 r;
  asm("mov.b64 {%0, %1}, %2;" : "=f"(r.x), "=f"(r.y) : "l"(v));
  return r;
}

// ---------------------------------------------------------------------------
// Kernel A: xg = x @ Wi  (unchanged, proven)
// ---------------------------------------------------------------------------
__global__ __launch_bounds__(256) void xg_gemm(const float* __restrict__ X,
                                               const float* __restrict__ Wi) {
  __shared__ float As[16][132];
  __shared__ float Bs[16][128];

  const int tid = threadIdx.x;
  const size_t mbase = (size_t)blockIdx.y * 128;
  const int nbase = blockIdx.x * 128;
  const float* A0 = X + mbase * Dd;
  const float* B0 = Wi + nbase;

  const int arow = tid >> 2;
  const int acol = (tid & 3) << 2;
  const int brow = tid >> 5;
  const int bcol = (tid & 31) << 2;
  const int tx = tid & 15;
  const int ty = tid >> 4;

  ull acc[8][4];
#pragma unroll
  for (int i = 0; i < 8; i++)
#pragma unroll
    for (int j = 0; j < 4; j++) acc[i][j] = 0ull;

  for (int k0 = 0; k0 < Dd; k0 += 16) {
#pragma unroll
    for (int i = 0; i < 2; i++) {
      float4 a = *(const float4*)(A0 + (size_t)(arow + i * 64) * Dd + k0 + acol);
      As[acol + 0][arow + i * 64] = a.x;
      As[acol + 1][arow + i * 64] = a.y;
      As[acol + 2][arow + i * 64] = a.z;
      As[acol + 3][arow + i * 64] = a.w;
    }
#pragma unroll
    for (int i = 0; i < 2; i++) {
      *(float4*)&Bs[brow + i * 8][bcol] =
          *(const float4*)(B0 + (size_t)(k0 + brow + i * 8) * Gg + bcol);
    }
    __syncthreads();
#pragma unroll
    for (int k = 0; k < 16; k++) {
      float ra[8];
      *(float4*)&ra[0] = *(const float4*)&As[k][ty * 8];
      *(float4*)&ra[4] = *(const float4*)&As[k][ty * 8 + 4];
      ulonglong2 rb0 = *(const ulonglong2*)&Bs[k][tx * 8];
      ulonglong2 rb1 = *(const ulonglong2*)&Bs[k][tx * 8 + 4];
#pragma unroll
      for (int i = 0; i < 8; i++) {
        ull ra2 = pack_dup(ra[i]);
        FMA2(acc[i][0], ra2, rb0.x);
        FMA2(acc[i][1], ra2, rb0.y);
        FMA2(acc[i][2], ra2, rb1.x);
        FMA2(acc[i][3], ra2, rb1.y);
      }
    }
    __syncthreads();
  }

  float* C = g_xg + (mbase + (size_t)ty * 8) * Gg + nbase + tx * 8;
#pragma unroll
  for (int i = 0; i < 8; i++) {
    float2 p0 = unpack2(acc[i][0]);
    float2 p1 = unpack2(acc[i][1]);
    float2 p2 = unpack2(acc[i][2]);
    float2 p3 = unpack2(acc[i][3]);
    *(float4*)(C + (size_t)i * Gg) = make_float4(p0.x, p0.y, p1.x, p1.y);
    *(float4*)(C + (size_t)i * Gg + 4) = make_float4(p2.x, p2.y, p3.x, p3.y);
  }
}

// ---------------------------------------------------------------------------
// Kernel B: persistent cluster LSTM — register-resident Wh + bulk-copy
// exchange with mbarrier tx accounting (no cluster rendezvous).
//
// 16 clusters x 8 CTAs x 512 threads. CTA r owns gate cols {g*256+r*32..+32}.
// GEMM: thread (ks=tid>>6, cc=tid&63) -> cols {cc,cc+64} x 8 batches over
//   k in [ks*32, ks*32+32). Its 64 Wh values are loop-invariant -> registers.
//   h layout [rank][batch][32] so slice ks == rank ks's contiguous block.
// Update (tid<256): thread (ub,jj) owns one h element; stages h in a 1KB
//   contiguous buffer. Threads 0..7 each issue ONE 1KB
//   cp.async.bulk.shared::cluster to rank tid, complete_tx on its mbar.
// Consumer: try_wait parity (expect_tx 8192/phase, re-armed post-wait).
// ---------------------------------------------------------------------------

// SMEM float offsets
#define HB_OFF 0         // [2][8 rank][8 b][32] = 4096 floats
#define PART_OFF 4096    // [8 ks][8 b][128 col] = 8192
#define HST_OFF 12288    // [2][8 b][32]         =  512
#define SMEM_FLOATS 12800
#define MB_BYTE (SMEM_FLOATS * 4)  // 2 mbarriers (16 B)
#define SMEM_BYTES (MB_BYTE + 16)

__device__ __forceinline__ void mbar_init_(uint32_t a, uint32_t cnt) {
  asm volatile("mbarrier.init.shared.b64 [%0], %1;" ::"r"(a), "r"(cnt)
               : "memory");
}
__device__ __forceinline__ void mbar_expect_tx(uint32_t a, uint32_t tx) {
  asm volatile("mbarrier.arrive.expect_tx.shared.b64 _, [%0], %1;" ::"r"(a),
               "r"(tx)
               : "memory");
}
__device__ __forceinline__ void mbar_wait(uint32_t mbar, uint32_t parity) {
  asm volatile(
      "{\n\t"
      ".reg .pred P;\n\t"
      "WL_%=:\n\t"
      "mbarrier.try_wait.parity.acquire.cluster.shared::cta.b64 P, [%0], %1, 0x989680;\n\t"
      "@P bra.uni WD_%=;\n\t"
      "bra.uni WL_%=;\n\t"
      "WD_%=:\n\t"
      "}" ::"r"(mbar),
      "r"(parity)
      : "memory");
}
__device__ __forceinline__ uint32_t mapa_u32(uint32_t la, int rk) {
  uint32_t ra;
  asm("mapa.shared::cluster.u32 %0, %1, %2;" : "=r"(ra) : "r"(la), "r"(rk));
  return ra;
}
__device__ __forceinline__ void bulk_copy_cluster(uint32_t dst, uint32_t src,
                                                  uint32_t bytes,
                                                  uint32_t rmbar) {
  asm volatile(
      "cp.async.bulk.shared::cluster.shared::cta.mbarrier::complete_tx::bytes "
      "[%0], [%1], %2, [%3];" ::"r"(dst),
      "r"(src), "r"(bytes), "r"(rmbar)
      : "memory");
}

__device__ __forceinline__ float sigf(float x) {
  return __fdividef(1.f, 1.f + __expf(-x));
}
__device__ __forceinline__ float tanhf_(float x) {
  return __fdividef(2.f, 1.f + __expf(-2.f * x)) - 1.f;
}

__global__ __launch_bounds__(512, 1) __cluster_dims__(8, 1, 1)
void lstm_rec(const float* __restrict__ Wh, const float* __restrict__ bh,
              float* __restrict__ out) {
  extern __shared__ float sm[];
  float* hb = sm + HB_OFF;
  float* part = sm + PART_OFF;
  float* hst = sm + HST_OFF;

  const int r = blockIdx.x;   // cluster rank
  const int cl = blockIdx.y;  // cluster id
  const int tid = threadIdx.x;
  const uint32_t smb = (uint32_t)__cvta_generic_to_shared(sm);

  // ---- init ----
  for (int idx = tid; idx < 4096; idx += 512) hb[idx] = 0.f;
  if (tid == 0) {
    mbar_init_(smb + MB_BYTE, 1);
    mbar_init_(smb + MB_BYTE + 8, 1);
    mbar_expect_tx(smb + MB_BYTE, 8192);      // arm phase 0
    mbar_expect_tx(smb + MB_BYTE + 8, 8192);  // arm phase 0
  }

  // GEMM mapping + register-resident Wh slice (loop-invariant!)
  const int ks = tid >> 6;  // 0..7 == rank whose k-block this thread consumes
  const int cc = tid & 63;  // cols cc, cc+64 (CTA-local)
  const int gcol0 = ((cc >> 5) << 8) + (r << 5) + (cc & 31);
  const int gcol1 = (((cc + 64) >> 5) << 8) + (r << 5) + (cc & 31);
  ull w0x[8], w0y[8], w1x[8], w1y[8];
#pragma unroll
  for (int kk = 0; kk < 8; kk++) {
    int k0 = (ks << 5) + (kk << 2);
    w0x[kk] = pack2(Wh[(k0 + 0) * Gg + gcol0], Wh[(k0 + 1) * Gg + gcol0]);
    w0y[kk] = pack2(Wh[(k0 + 2) * Gg + gcol0], Wh[(k0 + 3) * Gg + gcol0]);
    w1x[kk] = pack2(Wh[(k0 + 0) * Gg + gcol1], Wh[(k0 + 1) * Gg + gcol1]);
    w1y[kk] = pack2(Wh[(k0 + 2) * Gg + gcol1], Wh[(k0 + 3) * Gg + gcol1]);
  }

  // update mapping (threads 0..255)
  const bool upd = tid < 256;
  const int ub = (tid >> 5) & 7;
  const int jj = tid & 31;
  const int m = (r << 5) + jj;
  float breg[4];
#pragma unroll
  for (int g = 0; g < 4; g++) breg[g] = bh[(g << 8) + m];

  cg::this_cluster().sync();  // mbars + hb zeros visible before any copies

  float creg = 0.f;
  int ph0 = 0, ph1 = 0;
  const size_t OUT_FIN = (size_t)Bb * Tt * Hh;
  const size_t gb = (size_t)(cl << 3) + ub;
  const float* xgp = g_xg + gb * Tt * Gg + m;
  float* const out_base = out + (gb << 10) * Hh + m;

  for (int t = 0; t < Tt; t++) {
    const int q = t & 1;
    const int qn = q ^ 1;

    if (t) {
      uint32_t mb = smb + MB_BYTE + (q << 3);
      mbar_wait(mb, q ? ph1 : ph0);
      if (q) ph1 ^= 1; else ph0 ^= 1;
      if (tid == 0) mbar_expect_tx(mb, 8192);  // re-arm for use at t+2
    }

    // xg for this step: 4 coalesced LDGs, consumed after GEMM
    float xr0, xr1, xr2, xr3;
    if (upd) {
      const float* xp = xgp + (size_t)t * Gg;
      xr0 = __ldg(xp);
      xr1 = __ldg(xp + 256);
      xr2 = __ldg(xp + 512);
      xr3 = __ldg(xp + 768);
    }

    // ---- GEMM: h from smem (broadcast), w from registers ----
    {
      const ulonglong2* h2 =
          (const ulonglong2*)(hb + q * 2048) + (ks << 6);  // rank ks block
      ull acc[8][2];
#pragma unroll
      for (int b = 0; b < 8; b++) { acc[b][0] = 0ull; acc[b][1] = 0ull; }

#pragma unroll
      for (int kk = 0; kk < 8; kk++) {
#pragma unroll
        for (int b = 0; b < 8; b++) {
          ulonglong2 hv = h2[(b << 3) + kk];
          FMA2(acc[b][0], hv.x, w0x[kk]);
          FMA2(acc[b][0], hv.y, w0y[kk]);
          FMA2(acc[b][1], hv.x, w1x[kk]);
          FMA2(acc[b][1], hv.y, w1y[kk]);
        }
      }
#pragma unroll
      for (int b = 0; b < 8; b++) {
        float2 s0 = unpack2(acc[b][0]);
        float2 s1 = unpack2(acc[b][1]);
        part[(ks << 10) + (b << 7) + cc] = s0.x + s0.y;
        part[(ks << 10) + (b << 7) + cc + 64] = s1.x + s1.y;
      }
    }

    __syncthreads();  // part RAW

    // ---- update (tid<256): reduce 8 k-partials per gate ----
    if (upd) {
      float g0 = xr0 + breg[0];
      float g1 = xr1 + breg[1];
      float g2 = xr2 + breg[2];
      float g3 = xr3 + breg[3];
#pragma unroll
      for (int s = 0; s < 8; s++) {
        const float* pc = part + (s << 10) + (ub << 7) + jj;
        g0 += pc[0];
        g1 += pc[32];
        g2 += pc[64];
        g3 += pc[96];
      }
      float iv = sigf(g0);
      float fv = sigf(g1);
      float zv = tanhf_(g2);
      float ov = sigf(g3);
      float cnew = fv * creg + iv * zv;
      creg = cnew;
      float hv = ov * tanhf_(cnew);

      if (t + 1 < Tt) hst[qn * 256 + (ub << 5) + jj] = hv;

      out_base[(size_t)t * Hh] = hv;
      if (t == Tt - 1) {
        out[OUT_FIN + gb * Hh + m] = cnew;
        out[OUT_FIN + (size_t)Bb * Hh + gb * Hh + m] = hv;
      }
    }

    __syncthreads();  // hst complete before bulk copies read it

    // ---- exchange: 8 x 1KB bulk copies, one per rank ----
    if (tid < 8 && t + 1 < Tt) {
      asm volatile("fence.proxy.async.shared::cta;" ::: "memory");
      uint32_t src = smb + ((HST_OFF + qn * 256) << 2);
      uint32_t dstl = smb + ((HB_OFF + qn * 2048 + (r << 8)) << 2);
      uint32_t mbl = smb + MB_BYTE + (qn << 3);
      bulk_copy_cluster(mapa_u32(dstl, tid), src, 1024, mapa_u32(mbl, tid));
    }
  }

  cg::this_cluster().sync();  // no CTA exits with peer traffic in flight
}

// ---------------------------------------------------------------------------
extern "C" void kernel_launch(void* const* d_in, const int* in_sizes, int n_in,
                              void* d_out, int out_size) {
  const float* x = (const float*)d_in[0];    // [B, T, D]
  const float* Wi = (const float*)d_in[1];   // [D, 4H]
  const float* Wh = (const float*)d_in[2];   // [H, 4H]
  const float* bh = (const float*)d_in[3];   // [4H]
  float* out = (float*)d_out;                // outputs | c_fin | h_fin

  dim3 gA(Gg / 128, (Bb * Tt) / 128);  // (8, 1024)
  xg_gemm<<<gA, 256>>>(x, Wi);

  cudaFuncSetAttribute(lstm_rec, cudaFuncAttributeMaxDynamicSharedMemorySize,
                       SMEM_BYTES);
  lstm_rec<<<dim3(8, 16), 512, SMEM_BYTES>>>(Wh, bh, out);
}

// round 13
// speedup vs baseline: 1.9869x; 1.0721x over previous
#include <cuda_runtime.h>
#include <cooperative_groups.h>
#include <cstdint>

namespace cg = cooperative_groups;

#define Bb 128
#define Tt 1024
#define Dd 256
#define Hh 256
#define Gg 1024  // 4H

typedef unsigned long long ull;

// 512 MB scratch for xg = x @ Wi
__device__ float g_xg[(size_t)Bb * Tt * Gg];

// ---- packed fp32x2 helpers (SASS FFMA2 — only reachable via PTX) ----
#define FMA2(d, a, b) \
  asm("fma.rn.f32x2 %0, %1, %2, %0;" : "+l"(d) : "l"(a), "l"(b))

__device__ __forceinline__ ull pack_dup(float x) {
  ull d;
  unsigned u = __float_as_uint(x);
  asm("mov.b64 %0, {%1, %1};" : "=l"(d) : "r"(u));
  return d;
}
__device__ __forceinline__ ull pack2(float a, float b) {
  ull d;
  asm("mov.b64 %0, {%1, %2};" : "=l"(d) : "f"(a), "f"(b));
  return d;
}
__device__ __forceinline__ float2 unpack2(ull v) {
  float2 r;
  asm("mov.b64 {%0, %1}, %2;" : "=f"(r.x), "=f"(r.y) : "l"(v));
  return r;
}

// ---------------------------------------------------------------------------
// Kernel A: xg = x @ Wi  (unchanged, proven)
// ---------------------------------------------------------------------------
__global__ __launch_bounds__(256) void xg_gemm(const float* __restrict__ X,
                                               const float* __restrict__ Wi) {
  __shared__ float As[16][132];
  __shared__ float Bs[16][128];

  const int tid = threadIdx.x;
  const size_t mbase = (size_t)blockIdx.y * 128;
  const int nbase = blockIdx.x * 128;
  const float* A0 = X + mbase * Dd;
  const float* B0 = Wi + nbase;

  const int arow = tid >> 2;
  const int acol = (tid & 3) << 2;
  const int brow = tid >> 5;
  const int bcol = (tid & 31) << 2;
  const int tx = tid & 15;
  const int ty = tid >> 4;

  ull acc[8][4];
#pragma unroll
  for (int i = 0; i < 8; i++)
#pragma unroll
    for (int j = 0; j < 4; j++) acc[i][j] = 0ull;

  for (int k0 = 0; k0 < Dd; k0 += 16) {
#pragma unroll
    for (int i = 0; i < 2; i++) {
      float4 a = *(const float4*)(A0 + (size_t)(arow + i * 64) * Dd + k0 + acol);
      As[acol + 0][arow + i * 64] = a.x;
      As[acol + 1][arow + i * 64] = a.y;
      As[acol + 2][arow + i * 64] = a.z;
      As[acol + 3][arow + i * 64] = a.w;
    }
#pragma unroll
    for (int i = 0; i < 2; i++) {
      *(float4*)&Bs[brow + i * 8][bcol] =
          *(const float4*)(B0 + (size_t)(k0 + brow + i * 8) * Gg + bcol);
    }
    __syncthreads();
#pragma unroll
    for (int k = 0; k < 16; k++) {
      float ra[8];
      *(float4*)&ra[0] = *(const float4*)&As[k][ty * 8];
      *(float4*)&ra[4] = *(const float4*)&As[k][ty * 8 + 4];
      ulonglong2 rb0 = *(const ulonglong2*)&Bs[k][tx * 8];
      ulonglong2 rb1 = *(const ulonglong2*)&Bs[k][tx * 8 + 4];
#pragma unroll
      for (int i = 0; i < 8; i++) {
        ull ra2 = pack_dup(ra[i]);
        FMA2(acc[i][0], ra2, rb0.x);
        FMA2(acc[i][1], ra2, rb0.y);
        FMA2(acc[i][2], ra2, rb1.x);
        FMA2(acc[i][3], ra2, rb1.y);
      }
    }
    __syncthreads();
  }

  float* C = g_xg + (mbase + (size_t)ty * 8) * Gg + nbase + tx * 8;
#pragma unroll
  for (int i = 0; i < 8; i++) {
    float2 p0 = unpack2(acc[i][0]);
    float2 p1 = unpack2(acc[i][1]);
    float2 p2 = unpack2(acc[i][2]);
    float2 p3 = unpack2(acc[i][3]);
    *(float4*)(C + (size_t)i * Gg) = make_float4(p0.x, p0.y, p1.x, p1.y);
    *(float4*)(C + (size_t)i * Gg + 4) = make_float4(p2.x, p2.y, p3.x, p3.y);
  }
}

// ---------------------------------------------------------------------------
// Kernel B: persistent cluster LSTM — two batch groups software-pipelined
// over R12's register-Wh + bulk-copy + mbarrier-tx infrastructure.
//
// 16 clusters x 8 CTAs x 512 threads. CTA r owns gate cols {g*256+r*32..+32}.
// Group A = cluster batches 0-3, group B = 4-7 (independent chains).
// Per step: waitA,gemmA,updA,copyA | waitB,gemmB,updB,copyB — group A's
// fabric delivery overlaps group B's compute and vice versa.
// GEMM: thread (ks=tid>>6, cc=tid&63) -> cols {cc,cc+64} x 4 batches over
//   k in [ks*32,+32); 64 Wh values in registers (loop-invariant).
// Update: warps 0-3 own group A elements, warps 4-7 group B.
// Exchange: 8 x 512B cp.async.bulk.shared::cluster per group, complete_tx
//   on dest mbar (expect_tx 4096/phase), try_wait consumer. No rendezvous.
// ---------------------------------------------------------------------------

// SMEM float offsets
#define HBA_OFF 0        // [2][8 rank][4 b][32 k] = 2048
#define HBB_OFF 2048     // [2][8 rank][4 b][32 k] = 2048
#define PARTA_OFF 4096   // [8 ks][4 b][128 col]   = 4096
#define PARTB_OFF 8192   // [8 ks][4 b][128 col]   = 4096
#define HSTA_OFF 12288   // [2][4 b][32]           =  256
#define HSTB_OFF 12544   // [2][4 b][32]           =  256
#define SMEM_FLOATS 12800
#define MB_BYTE (SMEM_FLOATS * 4)  // 4 mbarriers: A0 A1 B0 B1
#define SMEM_BYTES (MB_BYTE + 32)

__device__ __forceinline__ void mbar_init_(uint32_t a, uint32_t cnt) {
  asm volatile("mbarrier.init.shared.b64 [%0], %1;" ::"r"(a), "r"(cnt)
               : "memory");
}
__device__ __forceinline__ void mbar_expect_tx(uint32_t a, uint32_t tx) {
  asm volatile("mbarrier.arrive.expect_tx.shared.b64 _, [%0], %1;" ::"r"(a),
               "r"(tx)
               : "memory");
}
__device__ __forceinline__ void mbar_wait(uint32_t mbar, uint32_t parity) {
  asm volatile(
      "{\n\t"
      ".reg .pred P;\n\t"
      "WL_%=:\n\t"
      "mbarrier.try_wait.parity.acquire.cluster.shared::cta.b64 P, [%0], %1, 0x989680;\n\t"
      "@P bra.uni WD_%=;\n\t"
      "bra.uni WL_%=;\n\t"
      "WD_%=:\n\t"
      "}" ::"r"(mbar),
      "r"(parity)
      : "memory");
}
__device__ __forceinline__ uint32_t mapa_u32(uint32_t la, int rk) {
  uint32_t ra;
  asm("mapa.shared::cluster.u32 %0, %1, %2;" : "=r"(ra) : "r"(la), "r"(rk));
  return ra;
}
__device__ __forceinline__ void bulk_copy_cluster(uint32_t dst, uint32_t src,
                                                  uint32_t bytes,
                                                  uint32_t rmbar) {
  asm volatile(
      "cp.async.bulk.shared::cluster.shared::cta.mbarrier::complete_tx::bytes "
      "[%0], [%1], %2, [%3];" ::"r"(dst),
      "r"(src), "r"(bytes), "r"(rmbar)
      : "memory");
}

__device__ __forceinline__ float sigf(float x) {
  return __fdividef(1.f, 1.f + __expf(-x));
}
__device__ __forceinline__ float tanhf_(float x) {
  return __fdividef(2.f, 1.f + __expf(-2.f * x)) - 1.f;
}

__global__ __launch_bounds__(512, 1) __cluster_dims__(8, 1, 1)
void lstm_rec(const float* __restrict__ Wh, const float* __restrict__ bh,
              float* __restrict__ out) {
  extern __shared__ float sm[];
  float* hbA = sm + HBA_OFF;
  float* hbB = sm + HBB_OFF;
  float* partA = sm + PARTA_OFF;
  float* partB = sm + PARTB_OFF;
  float* hstA = sm + HSTA_OFF;
  float* hstB = sm + HSTB_OFF;

  const int r = blockIdx.x;   // cluster rank
  const int cl = blockIdx.y;  // cluster id
  const int tid = threadIdx.x;
  const uint32_t smb = (uint32_t)__cvta_generic_to_shared(sm);

  // ---- init ----
  for (int idx = tid; idx < 4096; idx += 512) sm[idx] = 0.f;  // hbA + hbB
  if (tid == 0) {
#pragma unroll
    for (int i = 0; i < 4; i++) {
      mbar_init_(smb + MB_BYTE + (i << 3), 1);
      mbar_expect_tx(smb + MB_BYTE + (i << 3), 4096);  // arm phase 0
    }
  }

  // GEMM mapping + register-resident Wh slice (loop-invariant)
  const int ks = tid >> 6;  // 0..7: consumes rank ks's 32-k block
  const int cc = tid & 63;  // cols cc, cc+64 (CTA-local)
  const int gcol0 = ((cc >> 5) << 8) + (r << 5) + (cc & 31);
  const int gcol1 = (((cc + 64) >> 5) << 8) + (r << 5) + (cc & 31);
  ull w0x[8], w0y[8], w1x[8], w1y[8];
#pragma unroll
  for (int kk = 0; kk < 8; kk++) {
    int k0 = (ks << 5) + (kk << 2);
    w0x[kk] = pack2(Wh[(k0 + 0) * Gg + gcol0], Wh[(k0 + 1) * Gg + gcol0]);
    w0y[kk] = pack2(Wh[(k0 + 2) * Gg + gcol0], Wh[(k0 + 3) * Gg + gcol0]);
    w1x[kk] = pack2(Wh[(k0 + 0) * Gg + gcol1], Wh[(k0 + 1) * Gg + gcol1]);
    w1y[kk] = pack2(Wh[(k0 + 2) * Gg + gcol1], Wh[(k0 + 3) * Gg + gcol1]);
  }

  // update mapping: warps 0-3 -> group A, warps 4-7 -> group B
  const bool updA = tid < 128;
  const bool updB = tid >= 128 && tid < 256;
  const int ub = (tid >> 5) & 3;  // batch within group (0..3)
  const int jj = tid & 31;
  const int m = (r << 5) + jj;
  float breg[4];
#pragma unroll
  for (int g = 0; g < 4; g++) breg[g] = bh[(g << 8) + m];

  cg::this_cluster().sync();  // mbars + zeroed h visible before any copies

  float creg = 0.f;
  int phA0 = 0, phA1 = 0, phB0 = 0, phB1 = 0;
  const size_t OUT_FIN = (size_t)Bb * Tt * Hh;
  // group A: cluster batches 0-3; group B: 4-7
  const size_t gb = (size_t)(cl << 3) + (updB ? 4 : 0) + ub;
  const float* xgp = g_xg + gb * Tt * Gg + m;
  float* const out_base = out + (gb << 10) * Hh + m;

  for (int t = 0; t < Tt; t++) {
    const int q = t & 1;
    const int qn = q ^ 1;
    const uint32_t mbA = smb + MB_BYTE + (q << 3);
    const uint32_t mbB = smb + MB_BYTE + 16 + (q << 3);
    const uint32_t mbAn = smb + MB_BYTE + (qn << 3);
    const uint32_t mbBn = smb + MB_BYTE + 16 + (qn << 3);

    // xg loads for this step (both groups), hidden under wait + gemm
    float xr0, xr1, xr2, xr3;
    if (updA || updB) {
      const float* xp = xgp + (size_t)t * Gg;
      xr0 = __ldg(xp);
      xr1 = __ldg(xp + 256);
      xr2 = __ldg(xp + 512);
      xr3 = __ldg(xp + 768);
    }

    // ================= group A =================
    if (t) {
      mbar_wait(mbA, q ? phA1 : phA0);
      if (q) phA1 ^= 1; else phA0 ^= 1;
      if (tid == 0) mbar_expect_tx(mbA, 4096);  // re-arm for t+2
    }

    {  // gemm A: h from smem broadcast, w from registers
      const ulonglong2* h2 = (const ulonglong2*)(hbA + q * 1024) + (ks << 5);
      ull acc[4][2];
#pragma unroll
      for (int b = 0; b < 4; b++) { acc[b][0] = 0ull; acc[b][1] = 0ull; }
#pragma unroll
      for (int kk = 0; kk < 8; kk++) {
#pragma unroll
        for (int b = 0; b < 4; b++) {
          ulonglong2 hv = h2[(b << 3) + kk];
          FMA2(acc[b][0], hv.x, w0x[kk]);
          FMA2(acc[b][0], hv.y, w0y[kk]);
          FMA2(acc[b][1], hv.x, w1x[kk]);
          FMA2(acc[b][1], hv.y, w1y[kk]);
        }
      }
#pragma unroll
      for (int b = 0; b < 4; b++) {
        float2 s0 = unpack2(acc[b][0]);
        float2 s1 = unpack2(acc[b][1]);
        partA[(ks << 9) + (b << 7) + cc] = s0.x + s0.y;
        partA[(ks << 9) + (b << 7) + cc + 64] = s1.x + s1.y;
      }
    }
    __syncthreads();  // partA RAW

    if (updA) {
      float g0 = xr0 + breg[0];
      float g1 = xr1 + breg[1];
      float g2 = xr2 + breg[2];
      float g3 = xr3 + breg[3];
#pragma unroll
      for (int s = 0; s < 8; s++) {
        const float* pc = partA + (s << 9) + (ub << 7) + jj;
        g0 += pc[0];
        g1 += pc[32];
        g2 += pc[64];
        g3 += pc[96];
      }
      float iv = sigf(g0), fv = sigf(g1), zv = tanhf_(g2), ov = sigf(g3);
      float cnew = fv * creg + iv * zv;
      creg = cnew;
      float hv = ov * tanhf_(cnew);

      if (t + 1 < Tt) hstA[qn * 128 + (ub << 5) + jj] = hv;
      out_base[(size_t)t * Hh] = hv;
      if (t == Tt - 1) {
        out[OUT_FIN + gb * Hh + m] = cnew;
        out[OUT_FIN + (size_t)Bb * Hh + gb * Hh + m] = hv;
      }
    }
    __syncthreads();  // hstA ready before copies

    if (tid < 8 && t + 1 < Tt) {
      asm volatile("fence.proxy.async.shared::cta;" ::: "memory");
      uint32_t src = smb + ((HSTA_OFF + qn * 128) << 2);
      uint32_t dstl = smb + ((HBA_OFF + qn * 1024 + (r << 7)) << 2);
      bulk_copy_cluster(mapa_u32(dstl, tid), src, 512, mapa_u32(mbAn, tid));
    }

    // ================= group B =================
    if (t) {
      mbar_wait(mbB, q ? phB1 : phB0);
      if (q) phB1 ^= 1; else phB0 ^= 1;
      if (tid == 0) mbar_expect_tx(mbB, 4096);
    }

    {  // gemm B
      const ulonglong2* h2 = (const ulonglong2*)(hbB + q * 1024) + (ks << 5);
      ull acc[4][2];
#pragma unroll
      for (int b = 0; b < 4; b++) { acc[b][0] = 0ull; acc[b][1] = 0ull; }
#pragma unroll
      for (int kk = 0; kk < 8; kk++) {
#pragma unroll
        for (int b = 0; b < 4; b++) {
          ulonglong2 hv = h2[(b << 3) + kk];
          FMA2(acc[b][0], hv.x, w0x[kk]);
          FMA2(acc[b][0], hv.y, w0y[kk]);
          FMA2(acc[b][1], hv.x, w1x[kk]);
          FMA2(acc[b][1], hv.y, w1y[kk]);
        }
      }
#pragma unroll
      for (int b = 0; b < 4; b++) {
        float2 s0 = unpack2(acc[b][0]);
        float2 s1 = unpack2(acc[b][1]);
        partB[(ks << 9) + (b << 7) + cc] = s0.x + s0.y;
        partB[(ks << 9) + (b << 7) + cc + 64] = s1.x + s1.y;
      }
    }
    __syncthreads();  // partB RAW

    if (updB) {
      float g0 = xr0 + breg[0];
      float g1 = xr1 + breg[1];
      float g2 = xr2 + breg[2];
      float g3 = xr3 + breg[3];
#pragma unroll
      for (int s = 0; s < 8; s++) {
        const float* pc = partB + (s << 9) + (ub << 7) + jj;
        g0 += pc[0];
        g1 += pc[32];
        g2 += pc[64];
        g3 += pc[96];
      }
      float iv = sigf(g0), fv = sigf(g1), zv = tanhf_(g2), ov = sigf(g3);
      float cnew = fv * creg + iv * zv;
      creg = cnew;
      float hv = ov * tanhf_(cnew);

      if (t + 1 < Tt) hstB[qn * 128 + (ub << 5) + jj] = hv;
      out_base[(size_t)t * Hh] = hv;
      if (t == Tt - 1) {
        out[OUT_FIN + gb * Hh + m] = cnew;
        out[OUT_FIN + (size_t)Bb * Hh + gb * Hh + m] = hv;
      }
    }
    __syncthreads();  // hstB ready before copies

    if (tid < 8 && t + 1 < Tt) {
      asm volatile("fence.proxy.async.shared::cta;" ::: "memory");
      uint32_t src = smb + ((HSTB_OFF + qn * 128) << 2);
      uint32_t dstl = smb + ((HBB_OFF + qn * 1024 + (r << 7)) << 2);
      bulk_copy_cluster(mapa_u32(dstl, tid), src, 512, mapa_u32(mbBn, tid));
    }
  }

  cg::this_cluster().sync();  // no CTA exits with peer traffic in flight
}

// ---------------------------------------------------------------------------
extern "C" void kernel_launch(void* const* d_in, const int* in_sizes, int n_in,
                              void* d_out, int out_size) {
  const float* x = (const float*)d_in[0];    // [B, T, D]
  const float* Wi = (const float*)d_in[1];   // [D, 4H]
  const float* Wh = (const float*)d_in[2];   // [H, 4H]
  const float* bh = (const float*)d_in[3];   // [4H]
  float* out = (float*)d_out;                // outputs | c_fin | h_fin

  dim3 gA(Gg / 128, (Bb * Tt) / 128);  // (8, 1024)
  xg_gemm<<<gA, 256>>>(x, Wi);

  cudaFuncSetAttribute(lstm_rec, cudaFuncAttributeMaxDynamicSharedMemorySize,
                       SMEM_BYTES);
  lstm_rec<<<dim3(8, 16), 512, SMEM_BYTES>>>(Wh, bh, out);
}

// round 15
// speedup vs baseline: 2.1400x; 1.0771x over previous
#include <cuda_runtime.h>
#include <cuda_bf16.h>
#include <cooperative_groups.h>
#include <cstdint>

namespace cg = cooperative_groups;

#define Bb 128
#define Tt 1024
#define Dd 256
#define Hh 256
#define Gg 1024  // 4H

typedef unsigned long long ull;

// scratch: xg = x @ Wi (fp32), plus bf16 hi/lo split operands
__device__ float g_xg[(size_t)Bb * Tt * Gg];                 // 512 MB
__device__ __nv_bfloat16 g_xhi[(size_t)Bb * Tt * Dd];        // 64 MB
__device__ __nv_bfloat16 g_xlo[(size_t)Bb * Tt * Dd];        // 64 MB
__device__ __nv_bfloat16 g_whi[(size_t)Gg * Dd];             // [n][k] transposed
__device__ __nv_bfloat16 g_wlo[(size_t)Gg * Dd];

// ---- packed fp32x2 helpers (SASS FFMA2 — only reachable via PTX) ----
#define FMA2(d, a, b) \
  asm("fma.rn.f32x2 %0, %1, %2, %0;" : "+l"(d) : "l"(a), "l"(b))

__device__ __forceinline__ ull pack2(float a, float b) {
  ull d;
  asm("mov.b64 %0, {%1, %2};" : "=l"(d) : "f"(a), "f"(b));
  return d;
}
__device__ __forceinline__ float2 unpack2(ull v) {
  float2 r;
  asm("mov.b64 {%0, %1}, %2;" : "=f"(r.x), "=f"(r.y) : "l"(v));
  return r;
}

// ============================================================================
// Kernel A0: split x into bf16 hi/lo (elementwise, coalesced)
// ============================================================================
__global__ __launch_bounds__(256) void convert_x(const float* __restrict__ X) {
  size_t i = (size_t)blockIdx.x * 256 + threadIdx.x;  // float4 index
  float4 f = ((const float4*)X)[i];
  __nv_bfloat16 h0 = __float2bfloat16(f.x);
  __nv_bfloat16 h1 = __float2bfloat16(f.y);
  __nv_bfloat16 h2 = __float2bfloat16(f.z);
  __nv_bfloat16 h3 = __float2bfloat16(f.w);
  __nv_bfloat16 l0 = __float2bfloat16(f.x - __bfloat162float(h0));
  __nv_bfloat16 l1 = __float2bfloat16(f.y - __bfloat162float(h1));
  __nv_bfloat16 l2 = __float2bfloat16(f.z - __bfloat162float(h2));
  __nv_bfloat16 l3 = __float2bfloat16(f.w - __bfloat162float(h3));
  uint32_t hA = (uint32_t)*(uint16_t*)&h0 | ((uint32_t)*(uint16_t*)&h1 << 16);
  uint32_t hB = (uint32_t)*(uint16_t*)&h2 | ((uint32_t)*(uint16_t*)&h3 << 16);
  uint32_t lA = (uint32_t)*(uint16_t*)&l0 | ((uint32_t)*(uint16_t*)&l1 << 16);
  uint32_t lB = (uint32_t)*(uint16_t*)&l2 | ((uint32_t)*(uint16_t*)&l3 << 16);
  ((uint2*)g_xhi)[i] = make_uint2(hA, hB);
  ((uint2*)g_xlo)[i] = make_uint2(lA, lB);
}

// ============================================================================
// Kernel A0b: split + transpose Wi [k][n] -> g_whi/g_wlo [n][k]
// ============================================================================
__global__ __launch_bounds__(256) void convert_wi(const float* __restrict__ Wi) {
  __shared__ float tile[32][33];
  const int nt = blockIdx.x;  // 32 n-tiles
  const int kt = blockIdx.y;  // 8 k-tiles
  const int tx = threadIdx.x & 31;
  const int ty = threadIdx.x >> 5;  // 0..7
#pragma unroll
  for (int i = 0; i < 32; i += 8)
    tile[ty + i][tx] = Wi[(size_t)(kt * 32 + ty + i) * Gg + nt * 32 + tx];
  __syncthreads();
#pragma unroll
  for (int i = 0; i < 32; i += 8) {
    int n = nt * 32 + ty + i;
    int k = kt * 32 + tx;
    float v = tile[tx][ty + i];
    __nv_bfloat16 h = __float2bfloat16(v);
    __nv_bfloat16 l = __float2bfloat16(v - __bfloat162float(h));
    g_whi[(size_t)n * Dd + k] = h;
    g_wlo[(size_t)n * Dd + k] = l;
  }
}

// ============================================================================
// Kernel A1: xg = x @ Wi via mma.sync bf16x3 (HMMA tensor path).
// Grid (8 n-tiles, 1024 m-tiles), 256 threads = 8 warps (4m x 2n),
// warp tile 32m x 64n. BK=32, smem [row][40] bf16 (80B stride: 16B-aligned,
// conflict-free ldmatrix). Per k16: 48 mma (hh, lh, hl).
// ============================================================================
#define GA_KS 40

__device__ __forceinline__ void ldsm_x4(uint32_t* r, uint32_t addr) {
  asm volatile(
      "ldmatrix.sync.aligned.m8n8.x4.shared.b16 {%0,%1,%2,%3}, [%4];"
      : "=r"(r[0]), "=r"(r[1]), "=r"(r[2]), "=r"(r[3])
      : "r"(addr));
}
__device__ __forceinline__ void mma_bf16(float* c, const uint32_t* a,
                                         const uint32_t* b) {
  asm volatile(
      "mma.sync.aligned.m16n8k16.row.col.f32.bf16.bf16.f32 "
      "{%0,%1,%2,%3}, {%4,%5,%6,%7}, {%8,%9}, {%0,%1,%2,%3};"
      : "+f"(c[0]), "+f"(c[1]), "+f"(c[2]), "+f"(c[3])
      : "r"(a[0]), "r"(a[1]), "r"(a[2]), "r"(a[3]), "r"(b[0]), "r"(b[1]));
}

__global__ __launch_bounds__(256) void xg_hmma() {
  __shared__ __nv_bfloat16 sA[2][128 * GA_KS];
  __shared__ __nv_bfloat16 sB[2][128 * GA_KS];

  const int tid = threadIdx.x;
  const int lane = tid & 31;
  const int wid = tid >> 5;
  const int wm = wid & 3;   // m-warp 0..3
  const int wn = wid >> 2;  // n-warp 0..1
  const size_t mbase = (size_t)blockIdx.y * 128;
  const int nbase = blockIdx.x * 128;

  float acc[2][8][4];
#pragma unroll
  for (int i = 0; i < 2; i++)
#pragma unroll
    for (int j = 0; j < 8; j++)
#pragma unroll
      for (int v = 0; v < 4; v++) acc[i][j][v] = 0.f;

  // ldmatrix lane byte-offsets inside a [128][40] bf16 tile
  const int arow = lane & 15;
  const int acol = (lane >> 4) << 3;
  uint32_t aoff[2];
  aoff[0] = ((wm * 32 + arow) * GA_KS + acol) * 2;
  aoff[1] = ((wm * 32 + 16 + arow) * GA_KS + acol) * 2;

  const int brow = (lane & 7) + ((lane & 16) ? 8 : 0);
  const int bcol = (lane & 8) ? 8 : 0;
  uint32_t boff[4];
#pragma unroll
  for (int bq = 0; bq < 4; bq++)
    boff[bq] = ((wn * 64 + bq * 16 + brow) * GA_KS + bcol) * 2;

  const uint32_t sAh = (uint32_t)__cvta_generic_to_shared(sA[0]);
  const uint32_t sAl = (uint32_t)__cvta_generic_to_shared(sA[1]);
  const uint32_t sBh = (uint32_t)__cvta_generic_to_shared(sB[0]);
  const uint32_t sBl = (uint32_t)__cvta_generic_to_shared(sB[1]);

  // fill mapping: thread pair per row, 16-elem halves
  const int lrow = tid >> 1;
  const int lhalf = (tid & 1) << 4;
  const uint32_t soff = (lrow * GA_KS + lhalf) * 2;  // smem byte offset

  for (int kc = 0; kc < 8; kc++) {
    __syncthreads();  // previous chunk's reads complete
    {
      size_t ak = (mbase + lrow) * Dd + kc * 32 + lhalf;
      size_t bk = ((size_t)nbase + lrow) * Dd + kc * 32 + lhalf;
      *(uint4*)((char*)sA[0] + soff) = *(const uint4*)(g_xhi + ak);
      *(uint4*)((char*)sA[0] + soff + 16) = *(const uint4*)(g_xhi + ak + 8);
      *(uint4*)((char*)sA[1] + soff) = *(const uint4*)(g_xlo + ak);
      *(uint4*)((char*)sA[1] + soff + 16) = *(const uint4*)(g_xlo + ak + 8);
      *(uint4*)((char*)sB[0] + soff) = *(const uint4*)(g_whi + bk);
      *(uint4*)((char*)sB[0] + soff + 16) = *(const uint4*)(g_whi + bk + 8);
      *(uint4*)((char*)sB[1] + soff) = *(const uint4*)(g_wlo + bk);
      *(uint4*)((char*)sB[1] + soff + 16) = *(const uint4*)(g_wlo + bk + 8);
    }
    __syncthreads();

#pragma unroll
    for (int ko = 0; ko < 2; ko++) {
      const uint32_t kb = ko * 32;  // 16 elems * 2 bytes
      uint32_t ah[2][4], al[2][4], bf[4][4];
      ldsm_x4(ah[0], sAh + aoff[0] + kb);
      ldsm_x4(ah[1], sAh + aoff[1] + kb);
      ldsm_x4(al[0], sAl + aoff[0] + kb);
      ldsm_x4(al[1], sAl + aoff[1] + kb);
#pragma unroll
      for (int bq = 0; bq < 4; bq++) ldsm_x4(bf[bq], sBh + boff[bq] + kb);
      // hh + lh on B_hi
#pragma unroll
      for (int mf = 0; mf < 2; mf++)
#pragma unroll
        for (int nf = 0; nf < 8; nf++)
          mma_bf16(acc[mf][nf], ah[mf], &bf[nf >> 1][(nf & 1) * 2]);
#pragma unroll
      for (int mf = 0; mf < 2; mf++)
#pragma unroll
        for (int nf = 0; nf < 8; nf++)
          mma_bf16(acc[mf][nf], al[mf], &bf[nf >> 1][(nf & 1) * 2]);
      // hl on B_lo
#pragma unroll
      for (int bq = 0; bq < 4; bq++) ldsm_x4(bf[bq], sBl + boff[bq] + kb);
#pragma unroll
      for (int mf = 0; mf < 2; mf++)
#pragma unroll
        for (int nf = 0; nf < 8; nf++)
          mma_bf16(acc[mf][nf], ah[mf], &bf[nf >> 1][(nf & 1) * 2]);
    }
  }

  // epilogue: c0,c1 -> (r, 2c), c2,c3 -> (r+8, 2c)
#pragma unroll
  for (int mf = 0; mf < 2; mf++) {
    int r0 = wm * 32 + mf * 16 + (lane >> 2);
#pragma unroll
    for (int nf = 0; nf < 8; nf++) {
      int cb = nbase + wn * 64 + nf * 8 + 2 * (lane & 3);
      *(float2*)(g_xg + (mbase + r0) * Gg + cb) =
          make_float2(acc[mf][nf][0], acc[mf][nf][1]);
      *(float2*)(g_xg + (mbase + r0 + 8) * Gg + cb) =
          make_float2(acc[mf][nf][2], acc[mf][nf][3]);
    }
  }
}

// ============================================================================
// Kernel B: byte-identical to R13 (two-group pipelined cluster LSTM).
// ============================================================================
#define HBA_OFF 0
#define HBB_OFF 2048
#define PARTA_OFF 4096
#define PARTB_OFF 8192
#define HSTA_OFF 12288
#define HSTB_OFF 12544
#define SMEM_FLOATS 12800
#define MB_BYTE (SMEM_FLOATS * 4)
#define SMEM_BYTES (MB_BYTE + 32)

__device__ __forceinline__ void mbar_init_(uint32_t a, uint32_t cnt) {
  asm volatile("mbarrier.init.shared.b64 [%0], %1;" ::"r"(a), "r"(cnt)
               : "memory");
}
__device__ __forceinline__ void mbar_expect_tx(uint32_t a, uint32_t tx) {
  asm volatile("mbarrier.arrive.expect_tx.shared.b64 _, [%0], %1;" ::"r"(a),
               "r"(tx)
               : "memory");
}
__device__ __forceinline__ void mbar_wait(uint32_t mbar, uint32_t parity) {
  asm volatile(
      "{\n\t"
      ".reg .pred P;\n\t"
      "WL_%=:\n\t"
      "mbarrier.try_wait.parity.acquire.cluster.shared::cta.b64 P, [%0], %1, 0x989680;\n\t"
      "@P bra.uni WD_%=;\n\t"
      "bra.uni WL_%=;\n\t"
      "WD_%=:\n\t"
      "}" ::"r"(mbar),
      "r"(parity)
      : "memory");
}
__device__ __forceinline__ uint32_t mapa_u32(uint32_t la, int rk) {
  uint32_t ra;
  asm("mapa.shared::cluster.u32 %0, %1, %2;" : "=r"(ra) : "r"(la), "r"(rk));
  return ra;
}
__device__ __forceinline__ void bulk_copy_cluster(uint32_t dst, uint32_t src,
                                                  uint32_t bytes,
                                                  uint32_t rmbar) {
  asm volatile(
      "cp.async.bulk.shared::cluster.shared::cta.mbarrier::complete_tx::bytes "
      "[%0], [%1], %2, [%3];" ::"r"(dst),
      "r"(src), "r"(bytes), "r"(rmbar)
      : "memory");
}

__device__ __forceinline__ float sigf(float x) {
  return __fdividef(1.f, 1.f + __expf(-x));
}
__device__ __forceinline__ float tanhf_(float x) {
  return __fdividef(2.f, 1.f + __expf(-2.f * x)) - 1.f;
}

__global__ __launch_bounds__(512, 1) __cluster_dims__(8, 1, 1)
void lstm_rec(const float* __restrict__ Wh, const float* __restrict__ bh,
              float* __restrict__ out) {
  extern __shared__ float sm[];
  float* hbA = sm + HBA_OFF;
  float* hbB = sm + HBB_OFF;
  float* partA = sm + PARTA_OFF;
  float* partB = sm + PARTB_OFF;
  float* hstA = sm + HSTA_OFF;
  float* hstB = sm + HSTB_OFF;

  const int r = blockIdx.x;
  const int cl = blockIdx.y;
  const int tid = threadIdx.x;
  const uint32_t smb = (uint32_t)__cvta_generic_to_shared(sm);

  for (int idx = tid; idx < 4096; idx += 512) sm[idx] = 0.f;
  if (tid == 0) {
#pragma unroll
    for (int i = 0; i < 4; i++) {
      mbar_init_(smb + MB_BYTE + (i << 3), 1);
      mbar_expect_tx(smb + MB_BYTE + (i << 3), 4096);
    }
  }

  const int ks = tid >> 6;
  const int cc = tid & 63;
  const int gcol0 = ((cc >> 5) << 8) + (r << 5) + (cc & 31);
  const int gcol1 = (((cc + 64) >> 5) << 8) + (r << 5) + (cc & 31);
  ull w0x[8], w0y[8], w1x[8], w1y[8];
#pragma unroll
  for (int kk = 0; kk < 8; kk++) {
    int k0 = (ks << 5) + (kk << 2);
    w0x[kk] = pack2(Wh[(k0 + 0) * Gg + gcol0], Wh[(k0 + 1) * Gg + gcol0]);
    w0y[kk] = pack2(Wh[(k0 + 2) * Gg + gcol0], Wh[(k0 + 3) * Gg + gcol0]);
    w1x[kk] = pack2(Wh[(k0 + 0) * Gg + gcol1], Wh[(k0 + 1) * Gg + gcol1]);
    w1y[kk] = pack2(Wh[(k0 + 2) * Gg + gcol1], Wh[(k0 + 3) * Gg + gcol1]);
  }

  const bool updA = tid < 128;
  const bool updB = tid >= 128 && tid < 256;
  const int ub = (tid >> 5) & 3;
  const int jj = tid & 31;
  const int m = (r << 5) + jj;
  float breg[4];
#pragma unroll
  for (int g = 0; g < 4; g++) breg[g] = bh[(g << 8) + m];

  cg::this_cluster().sync();

  float creg = 0.f;
  int phA0 = 0, phA1 = 0, phB0 = 0, phB1 = 0;
  const size_t OUT_FIN = (size_t)Bb * Tt * Hh;
  const size_t gb = (size_t)(cl << 3) + (updB ? 4 : 0) + ub;
  const float* xgp = g_xg + gb * Tt * Gg + m;
  float* const out_base = out + (gb << 10) * Hh + m;

  for (int t = 0; t < Tt; t++) {
    const int q = t & 1;
    const int qn = q ^ 1;
    const uint32_t mbA = smb + MB_BYTE + (q << 3);
    const uint32_t mbB = smb + MB_BYTE + 16 + (q << 3);
    const uint32_t mbAn = smb + MB_BYTE + (qn << 3);
    const uint32_t mbBn = smb + MB_BYTE + 16 + (qn << 3);

    float xr0, xr1, xr2, xr3;
    if (updA || updB) {
      const float* xp = xgp + (size_t)t * Gg;
      xr0 = __ldg(xp);
      xr1 = __ldg(xp + 256);
      xr2 = __ldg(xp + 512);
      xr3 = __ldg(xp + 768);
    }

    // ================= group A =================
    if (t) {
      mbar_wait(mbA, q ? phA1 : phA0);
      if (q) phA1 ^= 1; else phA0 ^= 1;
      if (tid == 0) mbar_expect_tx(mbA, 4096);
    }

    {
      const ulonglong2* h2 = (const ulonglong2*)(hbA + q * 1024) + (ks << 5);
      ull acc[4][2];
#pragma unroll
      for (int b = 0; b < 4; b++) { acc[b][0] = 0ull; acc[b][1] = 0ull; }
#pragma unroll
      for (int kk = 0; kk < 8; kk++) {
#pragma unroll
        for (int b = 0; b < 4; b++) {
          ulonglong2 hv = h2[(b << 3) + kk];
          FMA2(acc[b][0], hv.x, w0x[kk]);
          FMA2(acc[b][0], hv.y, w0y[kk]);
          FMA2(acc[b][1], hv.x, w1x[kk]);
          FMA2(acc[b][1], hv.y, w1y[kk]);
        }
      }
#pragma unroll
      for (int b = 0; b < 4; b++) {
        float2 s0 = unpack2(acc[b][0]);
        float2 s1 = unpack2(acc[b][1]);
        partA[(ks << 9) + (b << 7) + cc] = s0.x + s0.y;
        partA[(ks << 9) + (b << 7) + cc + 64] = s1.x + s1.y;
      }
    }
    __syncthreads();

    if (updA) {
      float g0 = xr0 + breg[0];
      float g1 = xr1 + breg[1];
      float g2 = xr2 + breg[2];
      float g3 = xr3 + breg[3];
#pragma unroll
      for (int s = 0; s < 8; s++) {
        const float* pc = partA + (s << 9) + (ub << 7) + jj;
        g0 += pc[0];
        g1 += pc[32];
        g2 += pc[64];
        g3 += pc[96];
      }
      float iv = sigf(g0), fv = sigf(g1), zv = tanhf_(g2), ov = sigf(g3);
      float cnew = fv * creg + iv * zv;
      creg = cnew;
      float hv = ov * tanhf_(cnew);

      if (t + 1 < Tt) hstA[qn * 128 + (ub << 5) + jj] = hv;
      out_base[(size_t)t * Hh] = hv;
      if (t == Tt - 1) {
        out[OUT_FIN + gb * Hh + m] = cnew;
        out[OUT_FIN + (size_t)Bb * Hh + gb * Hh + m] = hv;
      }
    }
    __syncthreads();

    if (tid < 8 && t + 1 < Tt) {
      asm volatile("fence.proxy.async.shared::cta;" ::: "memory");
      uint32_t src = smb + ((HSTA_OFF + qn * 128) << 2);
      uint32_t dstl = smb + ((HBA_OFF + qn * 1024 + (r << 7)) << 2);
      bulk_copy_cluster(mapa_u32(dstl, tid), src, 512, mapa_u32(mbAn, tid));
    }

    // ================= group B =================
    if (t) {
      mbar_wait(mbB, q ? phB1 : phB0);
      if (q) phB1 ^= 1; else phB0 ^= 1;
      if (tid == 0) mbar_expect_tx(mbB, 4096);
    }

    {
      const ulonglong2* h2 = (const ulonglong2*)(hbB + q * 1024) + (ks << 5);
      ull acc[4][2];
#pragma unroll
      for (int b = 0; b < 4; b++) { acc[b][0] = 0ull; acc[b][1] = 0ull; }
#pragma unroll
      for (int kk = 0; kk < 8; kk++) {
#pragma unroll
        for (int b = 0; b < 4; b++) {
          ulonglong2 hv = h2[(b << 3) + kk];
          FMA2(acc[b][0], hv.x, w0x[kk]);
          FMA2(acc[b][0], hv.y, w0y[kk]);
          FMA2(acc[b][1], hv.x, w1x[kk]);
          FMA2(acc[b][1], hv.y, w1y[kk]);
        }
      }
#pragma unroll
      for (int b = 0; b < 4; b++) {
        float2 s0 = unpack2(acc[b][0]);
        float2 s1 = unpack2(acc[b][1]);
        partB[(ks << 9) + (b << 7) + cc] = s0.x + s0.y;
        partB[(ks << 9) + (b << 7) + cc + 64] = s1.x + s1.y;
      }
    }
    __syncthreads();

    if (updB) {
      float g0 = xr0 + breg[0];
      float g1 = xr1 + breg[1];
      float g2 = xr2 + breg[2];
      float g3 = xr3 + breg[3];
#pragma unroll
      for (int s = 0; s < 8; s++) {
        const float* pc = partB + (s << 9) + (ub << 7) + jj;
        g0 += pc[0];
        g1 += pc[32];
        g2 += pc[64];
        g3 += pc[96];
      }
      float iv = sigf(g0), fv = sigf(g1), zv = tanhf_(g2), ov = sigf(g3);
      float cnew = fv * creg + iv * zv;
      creg = cnew;
      float hv = ov * tanhf_(cnew);

      if (t + 1 < Tt) hstB[qn * 128 + (ub << 5) + jj] = hv;
      out_base[(size_t)t * Hh] = hv;
      if (t == Tt - 1) {
        out[OUT_FIN + gb * Hh + m] = cnew;
        out[OUT_FIN + (size_t)Bb * Hh + gb * Hh + m] = hv;
      }
    }
    __syncthreads();

    if (tid < 8 && t + 1 < Tt) {
      asm volatile("fence.proxy.async.shared::cta;" ::: "memory");
      uint32_t src = smb + ((HSTB_OFF + qn * 128) << 2);
      uint32_t dstl = smb + ((HBB_OFF + qn * 1024 + (r << 7)) << 2);
      bulk_copy_cluster(mapa_u32(dstl, tid), src, 512, mapa_u32(mbBn, tid));
    }
  }

  cg::this_cluster().sync();
}

// ---------------------------------------------------------------------------
extern "C" void kernel_launch(void* const* d_in, const int* in_sizes, int n_in,
                              void* d_out, int out_size) {
  const float* x = (const float*)d_in[0];    // [B, T, D]
  const float* Wi = (const float*)d_in[1];   // [D, 4H]
  const float* Wh = (const float*)d_in[2];   // [H, 4H]
  const float* bh = (const float*)d_in[3];   // [4H]
  float* out = (float*)d_out;                // outputs | c_fin | h_fin

  // A0: bf16 hi/lo splits (x: 131072*256/4 float4s = 32768 blocks)
  convert_x<<<32768, 256>>>(x);
  convert_wi<<<dim3(32, 8), 256>>>(Wi);

  // A1: HMMA bf16x3 GEMM -> g_xg
  xg_hmma<<<dim3(8, 1024), 256>>>();

  // B: persistent cluster recurrence (unchanged R13)
  cudaFuncSetAttribute(lstm_rec, cudaFuncAttributeMaxDynamicSharedMemorySize,
                       SMEM_BYTES);
  lstm_rec<<<dim3(8, 16), 512, SMEM_BYTES>>>(Wh, bh, out);
}

// round 16
// speedup vs baseline: 2.5069x; 1.1715x over previous
#include <cuda_runtime.h>
#include <cuda_bf16.h>
#include <cooperative_groups.h>
#include <cstdint>

namespace cg = cooperative_groups;

#define Bb 128
#define Tt 1024
#define Dd 256
#define Hh 256
#define Gg 1024  // 4H

typedef unsigned long long ull;

// scratch: xg = x @ Wi (fp32), plus bf16 hi/lo split operands
__device__ float g_xg[(size_t)Bb * Tt * Gg];                 // 512 MB
__device__ __nv_bfloat16 g_xhi[(size_t)Bb * Tt * Dd];
__device__ __nv_bfloat16 g_xlo[(size_t)Bb * Tt * Dd];
__device__ __nv_bfloat16 g_whi[(size_t)Gg * Dd];             // [n][k] transposed
__device__ __nv_bfloat16 g_wlo[(size_t)Gg * Dd];

// ============================================================================
// Kernel A0: split x into bf16 hi/lo (elementwise, coalesced)
// ============================================================================
__global__ __launch_bounds__(256) void convert_x(const float* __restrict__ X) {
  size_t i = (size_t)blockIdx.x * 256 + threadIdx.x;  // float4 index
  float4 f = ((const float4*)X)[i];
  __nv_bfloat16 h0 = __float2bfloat16(f.x);
  __nv_bfloat16 h1 = __float2bfloat16(f.y);
  __nv_bfloat16 h2 = __float2bfloat16(f.z);
  __nv_bfloat16 h3 = __float2bfloat16(f.w);
  __nv_bfloat16 l0 = __float2bfloat16(f.x - __bfloat162float(h0));
  __nv_bfloat16 l1 = __float2bfloat16(f.y - __bfloat162float(h1));
  __nv_bfloat16 l2 = __float2bfloat16(f.z - __bfloat162float(h2));
  __nv_bfloat16 l3 = __float2bfloat16(f.w - __bfloat162float(h3));
  uint32_t hA = (uint32_t)*(uint16_t*)&h0 | ((uint32_t)*(uint16_t*)&h1 << 16);
  uint32_t hB = (uint32_t)*(uint16_t*)&h2 | ((uint32_t)*(uint16_t*)&h3 << 16);
  uint32_t lA = (uint32_t)*(uint16_t*)&l0 | ((uint32_t)*(uint16_t*)&l1 << 16);
  uint32_t lB = (uint32_t)*(uint16_t*)&l2 | ((uint32_t)*(uint16_t*)&l3 << 16);
  ((uint2*)g_xhi)[i] = make_uint2(hA, hB);
  ((uint2*)g_xlo)[i] = make_uint2(lA, lB);
}

// ============================================================================
// Kernel A0b: split + transpose Wi [k][n] -> g_whi/g_wlo [n][k]
// ============================================================================
__global__ __launch_bounds__(256) void convert_wi(const float* __restrict__ Wi) {
  __shared__ float tile[32][33];
  const int nt = blockIdx.x;
  const int kt = blockIdx.y;
  const int tx = threadIdx.x & 31;
  const int ty = threadIdx.x >> 5;
#pragma unroll
  for (int i = 0; i < 32; i += 8)
    tile[ty + i][tx] = Wi[(size_t)(kt * 32 + ty + i) * Gg + nt * 32 + tx];
  __syncthreads();
#pragma unroll
  for (int i = 0; i < 32; i += 8) {
    int n = nt * 32 + ty + i;
    int k = kt * 32 + tx;
    float v = tile[tx][ty + i];
    __nv_bfloat16 h = __float2bfloat16(v);
    __nv_bfloat16 l = __float2bfloat16(v - __bfloat162float(h));
    g_whi[(size_t)n * Dd + k] = h;
    g_wlo[(size_t)n * Dd + k] = l;
  }
}

// ============================================================================
// Shared HMMA helpers
// ============================================================================
#define GA_KS 40

__device__ __forceinline__ void ldsm_x4(uint32_t* r, uint32_t addr) {
  asm volatile(
      "ldmatrix.sync.aligned.m8n8.x4.shared.b16 {%0,%1,%2,%3}, [%4];"
      : "=r"(r[0]), "=r"(r[1]), "=r"(r[2]), "=r"(r[3])
      : "r"(addr));
}
__device__ __forceinline__ void mma_bf16(float* c, const uint32_t* a,
                                         const uint32_t* b) {
  asm volatile(
      "mma.sync.aligned.m16n8k16.row.col.f32.bf16.bf16.f32 "
      "{%0,%1,%2,%3}, {%4,%5,%6,%7}, {%8,%9}, {%0,%1,%2,%3};"
      : "+f"(c[0]), "+f"(c[1]), "+f"(c[2]), "+f"(c[3])
      : "r"(a[0]), "r"(a[1]), "r"(a[2]), "r"(a[3]), "r"(b[0]), "r"(b[1]));
}
__device__ __forceinline__ void split2(float x, float y, uint32_t& hi,
                                       uint32_t& lo) {
  __nv_bfloat16 hx = __float2bfloat16(x), hy = __float2bfloat16(y);
  __nv_bfloat16 lx = __float2bfloat16(x - __bfloat162float(hx));
  __nv_bfloat16 ly = __float2bfloat16(y - __bfloat162float(hy));
  hi = (uint32_t)*(uint16_t*)&hx | ((uint32_t)*(uint16_t*)&hy << 16);
  lo = (uint32_t)*(uint16_t*)&lx | ((uint32_t)*(uint16_t*)&ly << 16);
}

// ============================================================================
// Kernel A1: xg = x @ Wi via mma.sync bf16x3 (unchanged from R15, proven)
// ============================================================================
__global__ __launch_bounds__(256) void xg_hmma() {
  __shared__ __nv_bfloat16 sA[2][128 * GA_KS];
  __shared__ __nv_bfloat16 sB[2][128 * GA_KS];

  const int tid = threadIdx.x;
  const int lane = tid & 31;
  const int wid = tid >> 5;
  const int wm = wid & 3;
  const int wn = wid >> 2;
  const size_t mbase = (size_t)blockIdx.y * 128;
  const int nbase = blockIdx.x * 128;

  float acc[2][8][4];
#pragma unroll
  for (int i = 0; i < 2; i++)
#pragma unroll
    for (int j = 0; j < 8; j++)
#pragma unroll
      for (int v = 0; v < 4; v++) acc[i][j][v] = 0.f;

  const int arow = lane & 15;
  const int acol = (lane >> 4) << 3;
  uint32_t aoff[2];
  aoff[0] = ((wm * 32 + arow) * GA_KS + acol) * 2;
  aoff[1] = ((wm * 32 + 16 + arow) * GA_KS + acol) * 2;

  const int brow = (lane & 7) + ((lane & 16) ? 8 : 0);
  const int bcol = (lane & 8) ? 8 : 0;
  uint32_t boff[4];
#pragma unroll
  for (int bq = 0; bq < 4; bq++)
    boff[bq] = ((wn * 64 + bq * 16 + brow) * GA_KS + bcol) * 2;

  const uint32_t sAh = (uint32_t)__cvta_generic_to_shared(sA[0]);
  const uint32_t sAl = (uint32_t)__cvta_generic_to_shared(sA[1]);
  const uint32_t sBh = (uint32_t)__cvta_generic_to_shared(sB[0]);
  const uint32_t sBl = (uint32_t)__cvta_generic_to_shared(sB[1]);

  const int lrow = tid >> 1;
  const int lhalf = (tid & 1) << 4;
  const uint32_t soff = (lrow * GA_KS + lhalf) * 2;

  for (int kc = 0; kc < 8; kc++) {
    __syncthreads();
    {
      size_t ak = (mbase + lrow) * Dd + kc * 32 + lhalf;
      size_t bk = ((size_t)nbase + lrow) * Dd + kc * 32 + lhalf;
      *(uint4*)((char*)sA[0] + soff) = *(const uint4*)(g_xhi + ak);
      *(uint4*)((char*)sA[0] + soff + 16) = *(const uint4*)(g_xhi + ak + 8);
      *(uint4*)((char*)sA[1] + soff) = *(const uint4*)(g_xlo + ak);
      *(uint4*)((char*)sA[1] + soff + 16) = *(const uint4*)(g_xlo + ak + 8);
      *(uint4*)((char*)sB[0] + soff) = *(const uint4*)(g_whi + bk);
      *(uint4*)((char*)sB[0] + soff + 16) = *(const uint4*)(g_whi + bk + 8);
      *(uint4*)((char*)sB[1] + soff) = *(const uint4*)(g_wlo + bk);
      *(uint4*)((char*)sB[1] + soff + 16) = *(const uint4*)(g_wlo + bk + 8);
    }
    __syncthreads();

#pragma unroll
    for (int ko = 0; ko < 2; ko++) {
      const uint32_t kb = ko * 32;
      uint32_t ah[2][4], al[2][4], bf[4][4];
      ldsm_x4(ah[0], sAh + aoff[0] + kb);
      ldsm_x4(ah[1], sAh + aoff[1] + kb);
      ldsm_x4(al[0], sAl + aoff[0] + kb);
      ldsm_x4(al[1], sAl + aoff[1] + kb);
#pragma unroll
      for (int bq = 0; bq < 4; bq++) ldsm_x4(bf[bq], sBh + boff[bq] + kb);
#pragma unroll
      for (int mf = 0; mf < 2; mf++)
#pragma unroll
        for (int nf = 0; nf < 8; nf++)
          mma_bf16(acc[mf][nf], ah[mf], &bf[nf >> 1][(nf & 1) * 2]);
#pragma unroll
      for (int mf = 0; mf < 2; mf++)
#pragma unroll
        for (int nf = 0; nf < 8; nf++)
          mma_bf16(acc[mf][nf], al[mf], &bf[nf >> 1][(nf & 1) * 2]);
#pragma unroll
      for (int bq = 0; bq < 4; bq++) ldsm_x4(bf[bq], sBl + boff[bq] + kb);
#pragma unroll
      for (int mf = 0; mf < 2; mf++)
#pragma unroll
        for (int nf = 0; nf < 8; nf++)
          mma_bf16(acc[mf][nf], ah[mf], &bf[nf >> 1][(nf & 1) * 2]);
    }
  }

#pragma unroll
  for (int mf = 0; mf < 2; mf++) {
    int r0 = wm * 32 + mf * 16 + (lane >> 2);
#pragma unroll
    for (int nf = 0; nf < 8; nf++) {
      int cb = nbase + wn * 64 + nf * 8 + 2 * (lane & 3);
      *(float2*)(g_xg + (mbase + r0) * Gg + cb) =
          make_float2(acc[mf][nf][0], acc[mf][nf][1]);
      *(float2*)(g_xg + (mbase + r0 + 8) * Gg + cb) =
          make_float2(acc[mf][nf][2], acc[mf][nf][3]);
    }
  }
}

// ============================================================================
// Kernel B: HMMA-based persistent cluster LSTM, two pipelined batch groups.
// 16 clusters x 8 CTAs x 512 threads (16 warps). CTA r owns gate cols
// {g*256 + r*32 .. +32} (128 local cols = mma M).
// Warp (wm = w&7, wk = w>>3): M-tile cols [16wm,16wm+16), k-half wk.
// Wh A-fragments (bf16 hi+lo) preloaded in REGISTERS for all 1024 steps.
// h staged bf16 hi/lo: hb[q][rank][batch4][80bf16] (hi at 0, lo at +40,
// batch stride 80 = conflict-free B-frag LDS). n-slots 4-7 feed zeros.
// gates = Whhi*hhi + Whlo*hhi + Whhi*hlo (fp32 acc) -> part[2wk][128][10].
// Sync/exchange: R13 protocol, 8 x 640B bulk copies, expect_tx 5120.
// ============================================================================
#define HBA_B 0        // [2 q][8 rk][4 b][80 bf16] = 10240 B
#define HBB_B 10240
#define PARTA_B 20480  // [2 wk][128][10] f32 = 10240 B
#define PARTB_B 30720
#define HSTA_B 40960   // [2 q][4 b][80 bf16] = 1280 B
#define HSTB_B 42240
#define MBAR_B 43520   // 4 mbarriers: A0 A1 B0 B1
#define SMEMB_BYTES 43552

__device__ __forceinline__ void mbar_init_(uint32_t a, uint32_t cnt) {
  asm volatile("mbarrier.init.shared.b64 [%0], %1;" ::"r"(a), "r"(cnt)
               : "memory");
}
__device__ __forceinline__ void mbar_expect_tx(uint32_t a, uint32_t tx) {
  asm volatile("mbarrier.arrive.expect_tx.shared.b64 _, [%0], %1;" ::"r"(a),
               "r"(tx)
               : "memory");
}
__device__ __forceinline__ void mbar_wait(uint32_t mbar, uint32_t parity) {
  asm volatile(
      "{\n\t"
      ".reg .pred P;\n\t"
      "WL_%=:\n\t"
      "mbarrier.try_wait.parity.acquire.cluster.shared::cta.b64 P, [%0], %1, 0x989680;\n\t"
      "@P bra.uni WD_%=;\n\t"
      "bra.uni WL_%=;\n\t"
      "WD_%=:\n\t"
      "}" ::"r"(mbar),
      "r"(parity)
      : "memory");
}
__device__ __forceinline__ uint32_t mapa_u32(uint32_t la, int rk) {
  uint32_t ra;
  asm("mapa.shared::cluster.u32 %0, %1, %2;" : "=r"(ra) : "r"(la), "r"(rk));
  return ra;
}
__device__ __forceinline__ void bulk_copy_cluster(uint32_t dst, uint32_t src,
                                                  uint32_t bytes,
                                                  uint32_t rmbar) {
  asm volatile(
      "cp.async.bulk.shared::cluster.shared::cta.mbarrier::complete_tx::bytes "
      "[%0], [%1], %2, [%3];" ::"r"(dst),
      "r"(src), "r"(bytes), "r"(rmbar)
      : "memory");
}

__device__ __forceinline__ float sigf(float x) {
  return __fdividef(1.f, 1.f + __expf(-x));
}
__device__ __forceinline__ float tanhf_(float x) {
  return __fdividef(2.f, 1.f + __expf(-2.f * x)) - 1.f;
}

__global__ __launch_bounds__(512, 1) __cluster_dims__(8, 1, 1)
void lstm_rec(const float* __restrict__ Wh, const float* __restrict__ bh,
              float* __restrict__ out) {
  extern __shared__ char smc[];
  const int r = blockIdx.x;
  const int cl = blockIdx.y;
  const int tid = threadIdx.x;
  const uint32_t smb = (uint32_t)__cvta_generic_to_shared(smc);

  // zero hbA + hbB (20480 B)
  for (int i = tid; i < 5120; i += 512) ((uint32_t*)smc)[i] = 0u;
  if (tid == 0) {
#pragma unroll
    for (int i = 0; i < 4; i++) {
      mbar_init_(smb + MBAR_B + (i << 3), 1);
      mbar_expect_tx(smb + MBAR_B + (i << 3), 5120);
    }
  }

  const int lane = tid & 31;
  const int gid = lane >> 2;
  const int qd = lane & 3;
  const int w = tid >> 5;
  const int wm = w & 7;
  const int wk = w >> 3;
  const int mm0 = wm * 16 + gid;
  const int mm1 = mm0 + 8;
  const int gc0 = ((mm0 >> 5) << 8) + (r << 5) + (mm0 & 31);
  const int gc1 = ((mm1 >> 5) << 8) + (r << 5) + (mm1 & 31);

  // Wh A-fragments in registers (loop-invariant): 8 kc x 4 regs x hi/lo
  uint32_t aHi[8][4], aLo[8][4];
#pragma unroll
  for (int kc = 0; kc < 8; kc++) {
    const int kb = wk * 128 + kc * 16 + qd * 2;
    split2(Wh[kb * Gg + gc0], Wh[(kb + 1) * Gg + gc0], aHi[kc][0], aLo[kc][0]);
    split2(Wh[kb * Gg + gc1], Wh[(kb + 1) * Gg + gc1], aHi[kc][1], aLo[kc][1]);
    split2(Wh[(kb + 8) * Gg + gc0], Wh[(kb + 9) * Gg + gc0], aHi[kc][2],
           aLo[kc][2]);
    split2(Wh[(kb + 8) * Gg + gc1], Wh[(kb + 9) * Gg + gc1], aHi[kc][3],
           aLo[kc][3]);
  }

  // update mapping: warps 0-3 -> group A (batches 0-3), 4-7 -> group B (4-7)
  const bool updA = tid < 128;
  const bool updB = tid >= 128 && tid < 256;
  const int ub = (tid >> 5) & 3;
  const int jj = tid & 31;
  const int m = (r << 5) + jj;
  float breg[4];
#pragma unroll
  for (int g = 0; g < 4; g++) breg[g] = bh[(g << 8) + m];

  cg::this_cluster().sync();

  float creg = 0.f;
  int phA0 = 0, phA1 = 0, phB0 = 0, phB1 = 0;
  const size_t OUT_FIN = (size_t)Bb * Tt * Hh;
  const size_t gb = (size_t)(cl << 3) + (updB ? 4 : 0) + ub;
  const float* xgp = g_xg + gb * Tt * Gg + m;
  float* const out_base = out + (gb << 10) * Hh + m;

  // per-lane byte offset inside a rank block for B-frag loads
  const int lboff = gid * 160 + qd * 4;

  for (int t = 0; t < Tt; t++) {
    const int q = t & 1;
    const int qn = q ^ 1;
    const uint32_t mbA = smb + MBAR_B + (q << 3);
    const uint32_t mbB = smb + MBAR_B + 16 + (q << 3);
    const uint32_t mbAn = smb + MBAR_B + (qn << 3);
    const uint32_t mbBn = smb + MBAR_B + 16 + (qn << 3);

    float xr0, xr1, xr2, xr3;
    if (updA || updB) {
      const float* xp = xgp + (size_t)t * Gg;
      xr0 = __ldg(xp);
      xr1 = __ldg(xp + 256);
      xr2 = __ldg(xp + 512);
      xr3 = __ldg(xp + 768);
    }

    // ================= group A =================
    if (t) {
      mbar_wait(mbA, q ? phA1 : phA0);
      if (q) phA1 ^= 1; else phA0 ^= 1;
      if (tid == 0) mbar_expect_tx(mbA, 5120);
    }

    {  // HMMA GEMM A
      float cacc[4] = {0.f, 0.f, 0.f, 0.f};
      const char* hbq = smc + HBA_B + q * 5120 + lboff;
#pragma unroll
      for (int kc = 0; kc < 8; kc++) {
        const int gkc = wk * 8 + kc;
        const char* p = hbq + (gkc >> 1) * 640 + (gkc & 1) * 32;
        uint32_t bhh[2] = {0u, 0u}, bll[2] = {0u, 0u};
        if (gid < 4) {
          bhh[0] = *(const uint32_t*)p;
          bhh[1] = *(const uint32_t*)(p + 16);
          bll[0] = *(const uint32_t*)(p + 80);
          bll[1] = *(const uint32_t*)(p + 96);
        }
        mma_bf16(cacc, aHi[kc], bhh);
        mma_bf16(cacc, aLo[kc], bhh);
        mma_bf16(cacc, aHi[kc], bll);
      }
      float* pA = (float*)(smc + PARTA_B) + wk * 1280;
      *(float2*)(pA + mm0 * 10 + qd * 2) = make_float2(cacc[0], cacc[1]);
      *(float2*)(pA + mm1 * 10 + qd * 2) = make_float2(cacc[2], cacc[3]);
    }
    __syncthreads();

    if (updA) {
      const float* pA = (const float*)(smc + PARTA_B);
      float g0 = xr0 + breg[0], g1 = xr1 + breg[1];
      float g2 = xr2 + breg[2], g3 = xr3 + breg[3];
      g0 += pA[(jj) * 10 + ub] + pA[1280 + (jj) * 10 + ub];
      g1 += pA[(32 + jj) * 10 + ub] + pA[1280 + (32 + jj) * 10 + ub];
      g2 += pA[(64 + jj) * 10 + ub] + pA[1280 + (64 + jj) * 10 + ub];
      g3 += pA[(96 + jj) * 10 + ub] + pA[1280 + (96 + jj) * 10 + ub];
      float iv = sigf(g0), fv = sigf(g1), zv = tanhf_(g2), ov = sigf(g3);
      float cnew = fv * creg + iv * zv;
      creg = cnew;
      float hv = ov * tanhf_(cnew);

      if (t + 1 < Tt) {
        __nv_bfloat16 hh = __float2bfloat16(hv);
        __nv_bfloat16 hl = __float2bfloat16(hv - __bfloat162float(hh));
        char* hs = smc + HSTA_B + qn * 640 + ub * 160 + jj * 2;
        *(__nv_bfloat16*)hs = hh;
        *(__nv_bfloat16*)(hs + 80) = hl;
      }
      out_base[(size_t)t * Hh] = hv;
      if (t == Tt - 1) {
        out[OUT_FIN + gb * Hh + m] = cnew;
        out[OUT_FIN + (size_t)Bb * Hh + gb * Hh + m] = hv;
      }
    }
    __syncthreads();

    if (tid < 8 && t + 1 < Tt) {
      asm volatile("fence.proxy.async.shared::cta;" ::: "memory");
      uint32_t src = smb + HSTA_B + qn * 640;
      uint32_t dstl = smb + HBA_B + qn * 5120 + r * 640;
      bulk_copy_cluster(mapa_u32(dstl, tid), src, 640, mapa_u32(mbAn, tid));
    }

    // ================= group B =================
    if (t) {
      mbar_wait(mbB, q ? phB1 : phB0);
      if (q) phB1 ^= 1; else phB0 ^= 1;
      if (tid == 0) mbar_expect_tx(mbB, 5120);
    }

    {  // HMMA GEMM B
      float cacc[4] = {0.f, 0.f, 0.f, 0.f};
      const char* hbq = smc + HBB_B + q * 5120 + lboff;
#pragma unroll
      for (int kc = 0; kc < 8; kc++) {
        const int gkc = wk * 8 + kc;
        const char* p = hbq + (gkc >> 1) * 640 + (gkc & 1) * 32;
        uint32_t bhh[2] = {0u, 0u}, bll[2] = {0u, 0u};
        if (gid < 4) {
          bhh[0] = *(const uint32_t*)p;
          bhh[1] = *(const uint32_t*)(p + 16);
          bll[0] = *(const uint32_t*)(p + 80);
          bll[1] = *(const uint32_t*)(p + 96);
        }
        mma_bf16(cacc, aHi[kc], bhh);
        mma_bf16(cacc, aLo[kc], bhh);
        mma_bf16(cacc, aHi[kc], bll);
      }
      float* pB = (float*)(smc + PARTB_B) + wk * 1280;
      *(float2*)(pB + mm0 * 10 + qd * 2) = make_float2(cacc[0], cacc[1]);
      *(float2*)(pB + mm1 * 10 + qd * 2) = make_float2(cacc[2], cacc[3]);
    }
    __syncthreads();

    if (updB) {
      const float* pB = (const float*)(smc + PARTB_B);
      float g0 = xr0 + breg[0], g1 = xr1 + breg[1];
      float g2 = xr2 + breg[2], g3 = xr3 + breg[3];
      g0 += pB[(jj) * 10 + ub] + pB[1280 + (jj) * 10 + ub];
      g1 += pB[(32 + jj) * 10 + ub] + pB[1280 + (32 + jj) * 10 + ub];
      g2 += pB[(64 + jj) * 10 + ub] + pB[1280 + (64 + jj) * 10 + ub];
      g3 += pB[(96 + jj) * 10 + ub] + pB[1280 + (96 + jj) * 10 + ub];
      float iv = sigf(g0), fv = sigf(g1), zv = tanhf_(g2), ov = sigf(g3);
      float cnew = fv * creg + iv * zv;
      creg = cnew;
      float hv = ov * tanhf_(cnew);

      if (t + 1 < Tt) {
        __nv_bfloat16 hh = __float2bfloat16(hv);
        __nv_bfloat16 hl = __float2bfloat16(hv - __bfloat162float(hh));
        char* hs = smc + HSTB_B + qn * 640 + ub * 160 + jj * 2;
        *(__nv_bfloat16*)hs = hh;
        *(__nv_bfloat16*)(hs + 80) = hl;
      }
      out_base[(size_t)t * Hh] = hv;
      if (t == Tt - 1) {
        out[OUT_FIN + gb * Hh + m] = cnew;
        out[OUT_FIN + (size_t)Bb * Hh + gb * Hh + m] = hv;
      }
    }
    __syncthreads();

    if (tid < 8 && t + 1 < Tt) {
      asm volatile("fence.proxy.async.shared::cta;" ::: "memory");
      uint32_t src = smb + HSTB_B + qn * 640;
      uint32_t dstl = smb + HBB_B + qn * 5120 + r * 640;
      bulk_copy_cluster(mapa_u32(dstl, tid), src, 640, mapa_u32(mbBn, tid));
    }
  }

  cg::this_cluster().sync();
}

// ---------------------------------------------------------------------------
extern "C" void kernel_launch(void* const* d_in, const int* in_sizes, int n_in,
                              void* d_out, int out_size) {
  const float* x = (const float*)d_in[0];    // [B, T, D]
  const float* Wi = (const float*)d_in[1];   // [D, 4H]
  const float* Wh = (const float*)d_in[2];   // [H, 4H]
  const float* bh = (const float*)d_in[3];   // [4H]
  float* out = (float*)d_out;                // outputs | c_fin | h_fin

  convert_x<<<32768, 256>>>(x);
  convert_wi<<<dim3(32, 8), 256>>>(Wi);
  xg_hmma<<<dim3(8, 1024), 256>>>();

  cudaFuncSetAttribute(lstm_rec, cudaFuncAttributeMaxDynamicSharedMemorySize,
                       SMEMB_BYTES);
  lstm_rec<<<dim3(8, 16), 512, SMEMB_BYTES>>>(Wh, bh, out);
}

// round 17
// speedup vs baseline: 2.5123x; 1.0021x over previous
#include <cuda_runtime.h>
#include <cuda_bf16.h>
#include <cooperative_groups.h>
#include <cstdint>

namespace cg = cooperative_groups;

#define Bb 128
#define Tt 1024
#define Dd 256
#define Hh 256
#define Gg 1024  // 4H

typedef unsigned long long ull;

// scratch: xg = x @ Wi (fp32), plus bf16 hi/lo split operands
__device__ float g_xg[(size_t)Bb * Tt * Gg];                 // 512 MB
__device__ __nv_bfloat16 g_xhi[(size_t)Bb * Tt * Dd];
__device__ __nv_bfloat16 g_xlo[(size_t)Bb * Tt * Dd];
__device__ __nv_bfloat16 g_whi[(size_t)Gg * Dd];             // [n][k] transposed
__device__ __nv_bfloat16 g_wlo[(size_t)Gg * Dd];

// ============================================================================
// Kernel A0: split x into bf16 hi/lo (elementwise, coalesced)
// ============================================================================
__global__ __launch_bounds__(256) void convert_x(const float* __restrict__ X) {
  size_t i = (size_t)blockIdx.x * 256 + threadIdx.x;  // float4 index
  float4 f = ((const float4*)X)[i];
  __nv_bfloat16 h0 = __float2bfloat16(f.x);
  __nv_bfloat16 h1 = __float2bfloat16(f.y);
  __nv_bfloat16 h2 = __float2bfloat16(f.z);
  __nv_bfloat16 h3 = __float2bfloat16(f.w);
  __nv_bfloat16 l0 = __float2bfloat16(f.x - __bfloat162float(h0));
  __nv_bfloat16 l1 = __float2bfloat16(f.y - __bfloat162float(h1));
  __nv_bfloat16 l2 = __float2bfloat16(f.z - __bfloat162float(h2));
  __nv_bfloat16 l3 = __float2bfloat16(f.w - __bfloat162float(h3));
  uint32_t hA = (uint32_t)*(uint16_t*)&h0 | ((uint32_t)*(uint16_t*)&h1 << 16);
  uint32_t hB = (uint32_t)*(uint16_t*)&h2 | ((uint32_t)*(uint16_t*)&h3 << 16);
  uint32_t lA = (uint32_t)*(uint16_t*)&l0 | ((uint32_t)*(uint16_t*)&l1 << 16);
  uint32_t lB = (uint32_t)*(uint16_t*)&l2 | ((uint32_t)*(uint16_t*)&l3 << 16);
  ((uint2*)g_xhi)[i] = make_uint2(hA, hB);
  ((uint2*)g_xlo)[i] = make_uint2(lA, lB);
}

// ============================================================================
// Kernel A0b: split + transpose Wi [k][n] -> g_whi/g_wlo [n][k]
// ============================================================================
__global__ __launch_bounds__(256) void convert_wi(const float* __restrict__ Wi) {
  __shared__ float tile[32][33];
  const int nt = blockIdx.x;
  const int kt = blockIdx.y;
  const int tx = threadIdx.x & 31;
  const int ty = threadIdx.x >> 5;
#pragma unroll
  for (int i = 0; i < 32; i += 8)
    tile[ty + i][tx] = Wi[(size_t)(kt * 32 + ty + i) * Gg + nt * 32 + tx];
  __syncthreads();
#pragma unroll
  for (int i = 0; i < 32; i += 8) {
    int n = nt * 32 + ty + i;
    int k = kt * 32 + tx;
    float v = tile[tx][ty + i];
    __nv_bfloat16 h = __float2bfloat16(v);
    __nv_bfloat16 l = __float2bfloat16(v - __bfloat162float(h));
    g_whi[(size_t)n * Dd + k] = h;
    g_wlo[(size_t)n * Dd + k] = l;
  }
}

// ============================================================================
// Shared HMMA helpers
// ============================================================================
#define GA_KS 40

__device__ __forceinline__ void ldsm_x4(uint32_t* r, uint32_t addr) {
  asm volatile(
      "ldmatrix.sync.aligned.m8n8.x4.shared.b16 {%0,%1,%2,%3}, [%4];"
      : "=r"(r[0]), "=r"(r[1]), "=r"(r[2]), "=r"(r[3])
      : "r"(addr));
}
__device__ __forceinline__ void mma_bf16(float* c, const uint32_t* a,
                                         const uint32_t* b) {
  asm volatile(
      "mma.sync.aligned.m16n8k16.row.col.f32.bf16.bf16.f32 "
      "{%0,%1,%2,%3}, {%4,%5,%6,%7}, {%8,%9}, {%0,%1,%2,%3};"
      : "+f"(c[0]), "+f"(c[1]), "+f"(c[2]), "+f"(c[3])
      : "r"(a[0]), "r"(a[1]), "r"(a[2]), "r"(a[3]), "r"(b[0]), "r"(b[1]));
}
__device__ __forceinline__ void split2(float x, float y, uint32_t& hi,
                                       uint32_t& lo) {
  __nv_bfloat16 hx = __float2bfloat16(x), hy = __float2bfloat16(y);
  __nv_bfloat16 lx = __float2bfloat16(x - __bfloat162float(hx));
  __nv_bfloat16 ly = __float2bfloat16(y - __bfloat162float(hy));
  hi = (uint32_t)*(uint16_t*)&hx | ((uint32_t)*(uint16_t*)&hy << 16);
  lo = (uint32_t)*(uint16_t*)&lx | ((uint32_t)*(uint16_t*)&ly << 16);
}

// ============================================================================
// Kernel A1: xg = x @ Wi via mma.sync bf16x3 (unchanged from R15, proven)
// ============================================================================
__global__ __launch_bounds__(256) void xg_hmma() {
  __shared__ __nv_bfloat16 sA[2][128 * GA_KS];
  __shared__ __nv_bfloat16 sB[2][128 * GA_KS];

  const int tid = threadIdx.x;
  const int lane = tid & 31;
  const int wid = tid >> 5;
  const int wm = wid & 3;
  const int wn = wid >> 2;
  const size_t mbase = (size_t)blockIdx.y * 128;
  const int nbase = blockIdx.x * 128;

  float acc[2][8][4];
#pragma unroll
  for (int i = 0; i < 2; i++)
#pragma unroll
    for (int j = 0; j < 8; j++)
#pragma unroll
      for (int v = 0; v < 4; v++) acc[i][j][v] = 0.f;

  const int arow = lane & 15;
  const int acol = (lane >> 4) << 3;
  uint32_t aoff[2];
  aoff[0] = ((wm * 32 + arow) * GA_KS + acol) * 2;
  aoff[1] = ((wm * 32 + 16 + arow) * GA_KS + acol) * 2;

  const int brow = (lane & 7) + ((lane & 16) ? 8 : 0);
  const int bcol = (lane & 8) ? 8 : 0;
  uint32_t boff[4];
#pragma unroll
  for (int bq = 0; bq < 4; bq++)
    boff[bq] = ((wn * 64 + bq * 16 + brow) * GA_KS + bcol) * 2;

  const uint32_t sAh = (uint32_t)__cvta_generic_to_shared(sA[0]);
  const uint32_t sAl = (uint32_t)__cvta_generic_to_shared(sA[1]);
  const uint32_t sBh = (uint32_t)__cvta_generic_to_shared(sB[0]);
  const uint32_t sBl = (uint32_t)__cvta_generic_to_shared(sB[1]);

  const int lrow = tid >> 1;
  const int lhalf = (tid & 1) << 4;
  const uint32_t soff = (lrow * GA_KS + lhalf) * 2;

  for (int kc = 0; kc < 8; kc++) {
    __syncthreads();
    {
      size_t ak = (mbase + lrow) * Dd + kc * 32 + lhalf;
      size_t bk = ((size_t)nbase + lrow) * Dd + kc * 32 + lhalf;
      *(uint4*)((char*)sA[0] + soff) = *(const uint4*)(g_xhi + ak);
      *(uint4*)((char*)sA[0] + soff + 16) = *(const uint4*)(g_xhi + ak + 8);
      *(uint4*)((char*)sA[1] + soff) = *(const uint4*)(g_xlo + ak);
      *(uint4*)((char*)sA[1] + soff + 16) = *(const uint4*)(g_xlo + ak + 8);
      *(uint4*)((char*)sB[0] + soff) = *(const uint4*)(g_whi + bk);
      *(uint4*)((char*)sB[0] + soff + 16) = *(const uint4*)(g_whi + bk + 8);
      *(uint4*)((char*)sB[1] + soff) = *(const uint4*)(g_wlo + bk);
      *(uint4*)((char*)sB[1] + soff + 16) = *(const uint4*)(g_wlo + bk + 8);
    }
    __syncthreads();

#pragma unroll
    for (int ko = 0; ko < 2; ko++) {
      const uint32_t kb = ko * 32;
      uint32_t ah[2][4], al[2][4], bf[4][4];
      ldsm_x4(ah[0], sAh + aoff[0] + kb);
      ldsm_x4(ah[1], sAh + aoff[1] + kb);
      ldsm_x4(al[0], sAl + aoff[0] + kb);
      ldsm_x4(al[1], sAl + aoff[1] + kb);
#pragma unroll
      for (int bq = 0; bq < 4; bq++) ldsm_x4(bf[bq], sBh + boff[bq] + kb);
#pragma unroll
      for (int mf = 0; mf < 2; mf++)
#pragma unroll
        for (int nf = 0; nf < 8; nf++)
          mma_bf16(acc[mf][nf], ah[mf], &bf[nf >> 1][(nf & 1) * 2]);
#pragma unroll
      for (int mf = 0; mf < 2; mf++)
#pragma unroll
        for (int nf = 0; nf < 8; nf++)
          mma_bf16(acc[mf][nf], al[mf], &bf[nf >> 1][(nf & 1) * 2]);
#pragma unroll
      for (int bq = 0; bq < 4; bq++) ldsm_x4(bf[bq], sBl + boff[bq] + kb);
#pragma unroll
      for (int mf = 0; mf < 2; mf++)
#pragma unroll
        for (int nf = 0; nf < 8; nf++)
          mma_bf16(acc[mf][nf], ah[mf], &bf[nf >> 1][(nf & 1) * 2]);
    }
  }

#pragma unroll
  for (int mf = 0; mf < 2; mf++) {
    int r0 = wm * 32 + mf * 16 + (lane >> 2);
#pragma unroll
    for (int nf = 0; nf < 8; nf++) {
      int cb = nbase + wn * 64 + nf * 8 + 2 * (lane & 3);
      *(float2*)(g_xg + (mbase + r0) * Gg + cb) =
          make_float2(acc[mf][nf][0], acc[mf][nf][1]);
      *(float2*)(g_xg + (mbase + r0 + 8) * Gg + cb) =
          make_float2(acc[mf][nf][2], acc[mf][nf][3]);
    }
  }
}

// ============================================================================
// Kernel B: HMMA cluster LSTM (R16 structure; GEMM accumulator split into
// 3 independent chains — hh / lh / hl — to break the 24-deep HMMA RAW chain).
// ============================================================================
#define HBA_B 0        // [2 q][8 rk][4 b][80 bf16] = 10240 B
#define HBB_B 10240
#define PARTA_B 20480  // [2 wk][128][10] f32 = 10240 B
#define PARTB_B 30720
#define HSTA_B 40960   // [2 q][4 b][80 bf16] = 1280 B
#define HSTB_B 42240
#define MBAR_B 43520   // 4 mbarriers: A0 A1 B0 B1
#define SMEMB_BYTES 43552

__device__ __forceinline__ void mbar_init_(uint32_t a, uint32_t cnt) {
  asm volatile("mbarrier.init.shared.b64 [%0], %1;" ::"r"(a), "r"(cnt)
               : "memory");
}
__device__ __forceinline__ void mbar_expect_tx(uint32_t a, uint32_t tx) {
  asm volatile("mbarrier.arrive.expect_tx.shared.b64 _, [%0], %1;" ::"r"(a),
               "r"(tx)
               : "memory");
}
__device__ __forceinline__ void mbar_wait(uint32_t mbar, uint32_t parity) {
  asm volatile(
      "{\n\t"
      ".reg .pred P;\n\t"
      "WL_%=:\n\t"
      "mbarrier.try_wait.parity.acquire.cluster.shared::cta.b64 P, [%0], %1, 0x989680;\n\t"
      "@P bra.uni WD_%=;\n\t"
      "bra.uni WL_%=;\n\t"
      "WD_%=:\n\t"
      "}" ::"r"(mbar),
      "r"(parity)
      : "memory");
}
__device__ __forceinline__ uint32_t mapa_u32(uint32_t la, int rk) {
  uint32_t ra;
  asm("mapa.shared::cluster.u32 %0, %1, %2;" : "=r"(ra) : "r"(la), "r"(rk));
  return ra;
}
__device__ __forceinline__ void bulk_copy_cluster(uint32_t dst, uint32_t src,
                                                  uint32_t bytes,
                                                  uint32_t rmbar) {
  asm volatile(
      "cp.async.bulk.shared::cluster.shared::cta.mbarrier::complete_tx::bytes "
      "[%0], [%1], %2, [%3];" ::"r"(dst),
      "r"(src), "r"(bytes), "r"(rmbar)
      : "memory");
}

__device__ __forceinline__ float sigf(float x) {
  return __fdividef(1.f, 1.f + __expf(-x));
}
__device__ __forceinline__ float tanhf_(float x) {
  return __fdividef(2.f, 1.f + __expf(-2.f * x)) - 1.f;
}

__global__ __launch_bounds__(512, 1) __cluster_dims__(8, 1, 1)
void lstm_rec(const float* __restrict__ Wh, const float* __restrict__ bh,
              float* __restrict__ out) {
  extern __shared__ char smc[];
  const int r = blockIdx.x;
  const int cl = blockIdx.y;
  const int tid = threadIdx.x;
  const uint32_t smb = (uint32_t)__cvta_generic_to_shared(smc);

  // zero hbA + hbB (20480 B)
  for (int i = tid; i < 5120; i += 512) ((uint32_t*)smc)[i] = 0u;
  if (tid == 0) {
#pragma unroll
    for (int i = 0; i < 4; i++) {
      mbar_init_(smb + MBAR_B + (i << 3), 1);
      mbar_expect_tx(smb + MBAR_B + (i << 3), 5120);
    }
  }

  const int lane = tid & 31;
  const int gid = lane >> 2;
  const int qd = lane & 3;
  const int w = tid >> 5;
  const int wm = w & 7;
  const int wk = w >> 3;
  const int mm0 = wm * 16 + gid;
  const int mm1 = mm0 + 8;
  const int gc0 = ((mm0 >> 5) << 8) + (r << 5) + (mm0 & 31);
  const int gc1 = ((mm1 >> 5) << 8) + (r << 5) + (mm1 & 31);

  // Wh A-fragments in registers (loop-invariant): 8 kc x 4 regs x hi/lo
  uint32_t aHi[8][4], aLo[8][4];
#pragma unroll
  for (int kc = 0; kc < 8; kc++) {
    const int kb = wk * 128 + kc * 16 + qd * 2;
    split2(Wh[kb * Gg + gc0], Wh[(kb + 1) * Gg + gc0], aHi[kc][0], aLo[kc][0]);
    split2(Wh[kb * Gg + gc1], Wh[(kb + 1) * Gg + gc1], aHi[kc][1], aLo[kc][1]);
    split2(Wh[(kb + 8) * Gg + gc0], Wh[(kb + 9) * Gg + gc0], aHi[kc][2],
           aLo[kc][2]);
    split2(Wh[(kb + 8) * Gg + gc1], Wh[(kb + 9) * Gg + gc1], aHi[kc][3],
           aLo[kc][3]);
  }

  // update mapping: warps 0-3 -> group A (batches 0-3), 4-7 -> group B (4-7)
  const bool updA = tid < 128;
  const bool updB = tid >= 128 && tid < 256;
  const int ub = (tid >> 5) & 3;
  const int jj = tid & 31;
  const int m = (r << 5) + jj;
  float breg[4];
#pragma unroll
  for (int g = 0; g < 4; g++) breg[g] = bh[(g << 8) + m];

  cg::this_cluster().sync();

  float creg = 0.f;
  int phA0 = 0, phA1 = 0, phB0 = 0, phB1 = 0;
  const size_t OUT_FIN = (size_t)Bb * Tt * Hh;
  const size_t gb = (size_t)(cl << 3) + (updB ? 4 : 0) + ub;
  const float* xgp = g_xg + gb * Tt * Gg + m;
  float* const out_base = out + (gb << 10) * Hh + m;

  // per-lane byte offset inside a rank block for B-frag loads
  const int lboff = gid * 160 + qd * 4;

  for (int t = 0; t < Tt; t++) {
    const int q = t & 1;
    const int qn = q ^ 1;
    const uint32_t mbA = smb + MBAR_B + (q << 3);
    const uint32_t mbB = smb + MBAR_B + 16 + (q << 3);
    const uint32_t mbAn = smb + MBAR_B + (qn << 3);
    const uint32_t mbBn = smb + MBAR_B + 16 + (qn << 3);

    float xr0, xr1, xr2, xr3;
    if (updA || updB) {
      const float* xp = xgp + (size_t)t * Gg;
      xr0 = __ldg(xp);
      xr1 = __ldg(xp + 256);
      xr2 = __ldg(xp + 512);
      xr3 = __ldg(xp + 768);
    }

    // ================= group A =================
    if (t) {
      mbar_wait(mbA, q ? phA1 : phA0);
      if (q) phA1 ^= 1; else phA0 ^= 1;
      if (tid == 0) mbar_expect_tx(mbA, 5120);
    }

    {  // HMMA GEMM A — 3 independent accumulator chains
      float c_hh[4] = {0.f, 0.f, 0.f, 0.f};
      float c_lh[4] = {0.f, 0.f, 0.f, 0.f};
      float c_hl[4] = {0.f, 0.f, 0.f, 0.f};
      const char* hbq = smc + HBA_B + q * 5120 + lboff;
#pragma unroll
      for (int kc = 0; kc < 8; kc++) {
        const int gkc = wk * 8 + kc;
        const char* p = hbq + (gkc >> 1) * 640 + (gkc & 1) * 32;
        uint32_t bhh[2] = {0u, 0u}, bll[2] = {0u, 0u};
        if (gid < 4) {
          bhh[0] = *(const uint32_t*)p;
          bhh[1] = *(const uint32_t*)(p + 16);
          bll[0] = *(const uint32_t*)(p + 80);
          bll[1] = *(const uint32_t*)(p + 96);
        }
        mma_bf16(c_hh, aHi[kc], bhh);
        mma_bf16(c_lh, aLo[kc], bhh);
        mma_bf16(c_hl, aHi[kc], bll);
      }
      float* pA = (float*)(smc + PARTA_B) + wk * 1280;
      *(float2*)(pA + mm0 * 10 + qd * 2) =
          make_float2(c_hh[0] + c_lh[0] + c_hl[0], c_hh[1] + c_lh[1] + c_hl[1]);
      *(float2*)(pA + mm1 * 10 + qd * 2) =
          make_float2(c_hh[2] + c_lh[2] + c_hl[2], c_hh[3] + c_lh[3] + c_hl[3]);
    }
    __syncthreads();

    if (updA) {
      const float* pA = (const float*)(smc + PARTA_B);
      float g0 = xr0 + breg[0], g1 = xr1 + breg[1];
      float g2 = xr2 + breg[2], g3 = xr3 + breg[3];
      g0 += pA[(jj) * 10 + ub] + pA[1280 + (jj) * 10 + ub];
      g1 += pA[(32 + jj) * 10 + ub] + pA[1280 + (32 + jj) * 10 + ub];
      g2 += pA[(64 + jj) * 10 + ub] + pA[1280 + (64 + jj) * 10 + ub];
      g3 += pA[(96 + jj) * 10 + ub] + pA[1280 + (96 + jj) * 10 + ub];
      float iv = sigf(g0), fv = sigf(g1), zv = tanhf_(g2), ov = sigf(g3);
      float cnew = fv * creg + iv * zv;
      creg = cnew;
      float hv = ov * tanhf_(cnew);

      if (t + 1 < Tt) {
        __nv_bfloat16 hh = __float2bfloat16(hv);
        __nv_bfloat16 hl = __float2bfloat16(hv - __bfloat162float(hh));
        char* hs = smc + HSTA_B + qn * 640 + ub * 160 + jj * 2;
        *(__nv_bfloat16*)hs = hh;
        *(__nv_bfloat16*)(hs + 80) = hl;
      }
      out_base[(size_t)t * Hh] = hv;
      if (t == Tt - 1) {
        out[OUT_FIN + gb * Hh + m] = cnew;
        out[OUT_FIN + (size_t)Bb * Hh + gb * Hh + m] = hv;
      }
    }
    __syncthreads();

    if (tid < 8 && t + 1 < Tt) {
      asm volatile("fence.proxy.async.shared::cta;" ::: "memory");
      uint32_t src = smb + HSTA_B + qn * 640;
      uint32_t dstl = smb + HBA_B + qn * 5120 + r * 640;
      bulk_copy_cluster(mapa_u32(dstl, tid), src, 640, mapa_u32(mbAn, tid));
    }

    // ================= group B =================
    if (t) {
      mbar_wait(mbB, q ? phB1 : phB0);
      if (q) phB1 ^= 1; else phB0 ^= 1;
      if (tid == 0) mbar_expect_tx(mbB, 5120);
    }

    {  // HMMA GEMM B — 3 independent accumulator chains
      float c_hh[4] = {0.f, 0.f, 0.f, 0.f};
      float c_lh[4] = {0.f, 0.f, 0.f, 0.f};
      float c_hl[4] = {0.f, 0.f, 0.f, 0.f};
      const char* hbq = smc + HBB_B + q * 5120 + lboff;
#pragma unroll
      for (int kc = 0; kc < 8; kc++) {
        const int gkc = wk * 8 + kc;
        const char* p = hbq + (gkc >> 1) * 640 + (gkc & 1) * 32;
        uint32_t bhh[2] = {0u, 0u}, bll[2] = {0u, 0u};
        if (gid < 4) {
          bhh[0] = *(const uint32_t*)p;
          bhh[1] = *(const uint32_t*)(p + 16);
          bll[0] = *(const uint32_t*)(p + 80);
          bll[1] = *(const uint32_t*)(p + 96);
        }
        mma_bf16(c_hh, aHi[kc], bhh);
        mma_bf16(c_lh, aLo[kc], bhh);
        mma_bf16(c_hl, aHi[kc], bll);
      }
      float* pB = (float*)(smc + PARTB_B) + wk * 1280;
      *(float2*)(pB + mm0 * 10 + qd * 2) =
          make_float2(c_hh[0] + c_lh[0] + c_hl[0], c_hh[1] + c_lh[1] + c_hl[1]);
      *(float2*)(pB + mm1 * 10 + qd * 2) =
          make_float2(c_hh[2] + c_lh[2] + c_hl[2], c_hh[3] + c_lh[3] + c_hl[3]);
    }
    __syncthreads();

    if (updB) {
      const float* pB = (const float*)(smc + PARTB_B);
      float g0 = xr0 + breg[0], g1 = xr1 + breg[1];
      float g2 = xr2 + breg[2], g3 = xr3 + breg[3];
      g0 += pB[(jj) * 10 + ub] + pB[1280 + (jj) * 10 + ub];
      g1 += pB[(32 + jj) * 10 + ub] + pB[1280 + (32 + jj) * 10 + ub];
      g2 += pB[(64 + jj) * 10 + ub] + pB[1280 + (64 + jj) * 10 + ub];
      g3 += pB[(96 + jj) * 10 + ub] + pB[1280 + (96 + jj) * 10 + ub];
      float iv = sigf(g0), fv = sigf(g1), zv = tanhf_(g2), ov = sigf(g3);
      float cnew = fv * creg + iv * zv;
      creg = cnew;
      float hv = ov * tanhf_(cnew);

      if (t + 1 < Tt) {
        __nv_bfloat16 hh = __float2bfloat16(hv);
        __nv_bfloat16 hl = __float2bfloat16(hv - __bfloat162float(hh));
        char* hs = smc + HSTB_B + qn * 640 + ub * 160 + jj * 2;
        *(__nv_bfloat16*)hs = hh;
        *(__nv_bfloat16*)(hs + 80) = hl;
      }
      out_base[(size_t)t * Hh] = hv;
      if (t == Tt - 1) {
        out[OUT_FIN + gb * Hh + m] = cnew;
        out[OUT_FIN + (size_t)Bb * Hh + gb * Hh + m] = hv;
      }
    }
    __syncthreads();

    if (tid < 8 && t + 1 < Tt) {
      asm volatile("fence.proxy.async.shared::cta;" ::: "memory");
      uint32_t src = smb + HSTB_B + qn * 640;
      uint32_t dstl = smb + HBB_B + qn * 5120 + r * 640;
      bulk_copy_cluster(mapa_u32(dstl, tid), src, 640, mapa_u32(mbBn, tid));
    }
  }

  cg::this_cluster().sync();
}

// ---------------------------------------------------------------------------
extern "C" void kernel_launch(void* const* d_in, const int* in_sizes, int n_in,
                              void* d_out, int out_size) {
  const float* x = (const float*)d_in[0];    // [B, T, D]
  const float* Wi = (const float*)d_in[1];   // [D, 4H]
  const float* Wh = (const float*)d_in[2];   // [H, 4H]
  const float* bh = (const float*)d_in[3];   // [4H]
  float* out = (float*)d_out;                // outputs | c_fin | h_fin

  convert_x<<<32768, 256>>>(x);
  convert_wi<<<dim3(32, 8), 256>>>(Wi);
  xg_hmma<<<dim3(8, 1024), 256>>>();

  cudaFuncSetAttribute(lstm_rec, cudaFuncAttributeMaxDynamicSharedMemorySize,
                       SMEMB_BYTES);
  lstm_rec<<<dim3(8, 16), 512, SMEMB_BYTES>>>(Wh, bh, out);
}